// round 1
// baseline (speedup 1.0000x reference)
#include <cuda_runtime.h>
#include <cuda_bf16.h>
#include <math.h>

// Problem constants
#define Bn 2
#define Sn 2048
#define En 2048
#define NQ 16
#define NKV 4
#define HD 128
#define WINDOW 512
#define Mrows (Bn*Sn)          // 4096

// Scratch (device globals; no allocation allowed)
__device__ float g_q[(size_t)Mrows * NQ * HD];     // 32 MB  [b,s,h,d]
__device__ float g_k[(size_t)Mrows * NKV * HD];    //  8 MB  [b,s,kh,d]
__device__ float g_v[(size_t)Mrows * NKV * HD];    //  8 MB
__device__ float g_attn[(size_t)Mrows * NQ * HD];  // 32 MB  [b,s,h,d]

// ---------------------------------------------------------------------------
// Tiled fp32 GEMM: C[M,N] = A[M,K] @ B[K,N] + bias[N]
// BM=BN=64, BK=16, 256 threads, 4x4 register tile per thread.
// M % 64 == 0, N % 64 == 0, K % 16 == 0 (holds for all our shapes).
// ---------------------------------------------------------------------------
__global__ __launch_bounds__(256) void gemm_bias_kernel(
    const float* __restrict__ A, const float* __restrict__ B,
    const float* __restrict__ bias, float* __restrict__ C,
    int M, int N, int K)
{
    __shared__ float As[16][64];
    __shared__ float Bs[16][64];

    const int tid = threadIdx.x;
    const int tx = tid & 15;   // N direction
    const int ty = tid >> 4;   // M direction
    const int row0 = blockIdx.y * 64;
    const int col0 = blockIdx.x * 64;

    float acc[4][4] = {};

    const int ar = tid >> 2;          // 0..63
    const int ac = (tid & 3) * 4;     // 0,4,8,12
    const int br = tid >> 4;          // 0..15
    const int bc = (tid & 15) * 4;    // 0..60

    for (int k0 = 0; k0 < K; k0 += 16) {
        // Load A tile 64x16, store transposed As[k][m]
        float4 av = *(const float4*)&A[(size_t)(row0 + ar) * K + k0 + ac];
        As[ac + 0][ar] = av.x;
        As[ac + 1][ar] = av.y;
        As[ac + 2][ar] = av.z;
        As[ac + 3][ar] = av.w;
        // Load B tile 16x64
        float4 bv = *(const float4*)&B[(size_t)(k0 + br) * N + col0 + bc];
        *(float4*)&Bs[br][bc] = bv;
        __syncthreads();

        #pragma unroll
        for (int kk = 0; kk < 16; ++kk) {
            float a[4], bb[4];
            #pragma unroll
            for (int m = 0; m < 4; ++m) a[m] = As[kk][ty * 4 + m];
            #pragma unroll
            for (int n = 0; n < 4; ++n) bb[n] = Bs[kk][tx * 4 + n];
            #pragma unroll
            for (int m = 0; m < 4; ++m)
                #pragma unroll
                for (int n = 0; n < 4; ++n)
                    acc[m][n] += a[m] * bb[n];
        }
        __syncthreads();
    }

    #pragma unroll
    for (int m = 0; m < 4; ++m) {
        const int row = row0 + ty * 4 + m;
        #pragma unroll
        for (int n = 0; n < 4; ++n) {
            const int col = col0 + tx * 4 + n;
            C[(size_t)row * N + col] = acc[m][n] + bias[col];
        }
    }
}

// ---------------------------------------------------------------------------
// RoPE in-place on x laid out [B*S, nh, 128]. One thread per (row, head, pair).
// Interleaved convention: out[2d] = xe*cos - xo*sin ; out[2d+1] = xe*sin + xo*cos
// ---------------------------------------------------------------------------
__global__ void rope_kernel(float* __restrict__ x, int nh, int total)
{
    int idx = blockIdx.x * blockDim.x + threadIdx.x;
    if (idx >= total) return;
    int d = idx & 63;                 // pair index 0..63
    int t = idx >> 6;                 // row*nh + h
    int row = t / nh;                 // b*S + s
    int pos = row & (Sn - 1);         // s  (S = 2048 is power of two)

    // freq = 10000^(-2d/128), angle = pos * freq   (all fp32, like reference)
    float freq = __expf(-(2.0f * (float)d / 128.0f) * 9.210340371976184f); // ln(10000)
    float ang = (float)pos * freq;
    float sv = sinf(ang);
    float cv = cosf(ang);

    float* p = x + (size_t)t * 128 + 2 * d;
    float xe = p[0], xo = p[1];
    p[0] = xe * cv - xo * sv;
    p[1] = xe * sv + xo * cv;
}

// ---------------------------------------------------------------------------
// Sliding-window causal GQA attention, online softmax.
// One warp per query position; 8 warps/block over consecutive positions so
// K/V rows hit L1. q/attn layout [b,s,h,128]; k/v layout [b,s,kh,128].
// ---------------------------------------------------------------------------
__global__ __launch_bounds__(256) void attn_kernel(
    const float* __restrict__ q, const float* __restrict__ k,
    const float* __restrict__ v, float* __restrict__ o)
{
    const int warp = threadIdx.x >> 5;
    const int lane = threadIdx.x & 31;
    const int i = blockIdx.x * 8 + warp;   // query position
    const int h = blockIdx.y;
    const int b = blockIdx.z;
    const int kvh = h >> 2;                 // NQ/NKV = 4

    const float scale = 0.08838834764831845f; // 1/sqrt(128)

    const size_t qoff = (((size_t)(b * Sn + i)) * NQ + h) * HD + lane * 4;
    float4 qv = *(const float4*)(q + qoff);
    qv.x *= scale; qv.y *= scale; qv.z *= scale; qv.w *= scale;

    int j0 = i - WINDOW; if (j0 < 0) j0 = 0;

    const float* kbase = k + ((size_t)b * Sn) * (NKV * HD) + kvh * HD + lane * 4;
    const float* vbase = v + ((size_t)b * Sn) * (NKV * HD) + kvh * HD + lane * 4;

    float m = -1e30f, l = 0.0f;
    float4 acc = make_float4(0.f, 0.f, 0.f, 0.f);

    for (int j = j0; j <= i; ++j) {
        float4 kv = *(const float4*)(kbase + (size_t)j * (NKV * HD));
        float s = qv.x * kv.x + qv.y * kv.y + qv.z * kv.z + qv.w * kv.w;
        s += __shfl_xor_sync(0xffffffffu, s, 16);
        s += __shfl_xor_sync(0xffffffffu, s, 8);
        s += __shfl_xor_sync(0xffffffffu, s, 4);
        s += __shfl_xor_sync(0xffffffffu, s, 2);
        s += __shfl_xor_sync(0xffffffffu, s, 1);

        float4 vv = *(const float4*)(vbase + (size_t)j * (NKV * HD));
        float mn = fmaxf(m, s);
        float corr = __expf(m - mn);
        float p = __expf(s - mn);
        l = l * corr + p;
        acc.x = acc.x * corr + p * vv.x;
        acc.y = acc.y * corr + p * vv.y;
        acc.z = acc.z * corr + p * vv.z;
        acc.w = acc.w * corr + p * vv.w;
        m = mn;
    }

    float inv = 1.0f / l;
    float4 r = make_float4(acc.x * inv, acc.y * inv, acc.z * inv, acc.w * inv);
    *(float4*)(o + qoff) = r;
}

// ---------------------------------------------------------------------------
extern "C" void kernel_launch(void* const* d_in, const int* in_sizes, int n_in,
                              void* d_out, int out_size)
{
    const float* x  = (const float*)d_in[0];
    const float* Wq = (const float*)d_in[1];
    const float* bq = (const float*)d_in[2];
    const float* Wk = (const float*)d_in[3];
    const float* bk = (const float*)d_in[4];
    const float* Wv = (const float*)d_in[5];
    const float* bv = (const float*)d_in[6];
    const float* Wo = (const float*)d_in[7];
    const float* bo = (const float*)d_in[8];
    float* out = (float*)d_out;

    float *qp, *kp, *vp, *ap;
    cudaGetSymbolAddress((void**)&qp, g_q);
    cudaGetSymbolAddress((void**)&kp, g_k);
    cudaGetSymbolAddress((void**)&vp, g_v);
    cudaGetSymbolAddress((void**)&ap, g_attn);

    // QKV projections
    {
        dim3 grid(2048 / 64, Mrows / 64);
        gemm_bias_kernel<<<grid, 256>>>(x, Wq, bq, qp, Mrows, 2048, En);
    }
    {
        dim3 grid(512 / 64, Mrows / 64);
        gemm_bias_kernel<<<grid, 256>>>(x, Wk, bk, kp, Mrows, 512, En);
        gemm_bias_kernel<<<grid, 256>>>(x, Wv, bv, vp, Mrows, 512, En);
    }

    // RoPE on q and k
    {
        int totq = Mrows * NQ * 64;
        rope_kernel<<<(totq + 255) / 256, 256>>>(qp, NQ, totq);
        int totk = Mrows * NKV * 64;
        rope_kernel<<<(totk + 255) / 256, 256>>>(kp, NKV, totk);
    }

    // Attention
    {
        dim3 grid(Sn / 8, NQ, Bn);
        attn_kernel<<<grid, 256>>>(qp, kp, vp, ap);
    }

    // Output projection
    {
        dim3 grid(2048 / 64, Mrows / 64);
        gemm_bias_kernel<<<grid, 256>>>(ap, Wo, bo, out, Mrows, 2048, En);
    }
}

// round 3
// speedup vs baseline: 1.7771x; 1.7771x over previous
#include <cuda_runtime.h>
#include <cuda_bf16.h>
#include <math.h>
#include <cstdint>

// Problem constants
#define Bn 2
#define Sn 2048
#define En 2048
#define NQ 16
#define NKV 4
#define HD 128
#define WINDOW 512
#define Mrows (Bn*Sn)          // 4096

// ---------------------------------------------------------------------------
// Scratch (device globals; no allocation allowed)
// ---------------------------------------------------------------------------
__device__ float g_q[(size_t)Mrows * NQ * HD];     // 32 MB  [b,s,h,d]
__device__ float g_k[(size_t)Mrows * NKV * HD];    //  8 MB
__device__ float g_v[(size_t)Mrows * NKV * HD];    //  8 MB
__device__ float g_attn[(size_t)Mrows * NQ * HD];  // 32 MB

// split-bf16 copies
__device__ __nv_bfloat16 g_xh[(size_t)Mrows * En];
__device__ __nv_bfloat16 g_xl[(size_t)Mrows * En];
__device__ __nv_bfloat16 g_ah[(size_t)Mrows * En];
__device__ __nv_bfloat16 g_al[(size_t)Mrows * En];
// weights, transposed to [N, K]
__device__ __nv_bfloat16 g_wqh[(size_t)2048 * 2048];
__device__ __nv_bfloat16 g_wql[(size_t)2048 * 2048];
__device__ __nv_bfloat16 g_wkh[(size_t)512 * 2048];
__device__ __nv_bfloat16 g_wkl[(size_t)512 * 2048];
__device__ __nv_bfloat16 g_wvh[(size_t)512 * 2048];
__device__ __nv_bfloat16 g_wvl[(size_t)512 * 2048];
__device__ __nv_bfloat16 g_woh[(size_t)2048 * 2048];
__device__ __nv_bfloat16 g_wol[(size_t)2048 * 2048];

// ---------------------------------------------------------------------------
// PTX helpers (base sm_103 features only: mma.sync / ldmatrix / cp.async)
// ---------------------------------------------------------------------------
__device__ __forceinline__ uint32_t smem_to_u32(const void* p) {
    uint32_t a;
    asm("{ .reg .u64 t; cvta.to.shared.u64 t, %1; cvt.u32.u64 %0, t; }" : "=r"(a) : "l"(p));
    return a;
}
__device__ __forceinline__ void ldsm4(uint32_t* r, uint32_t addr) {
    asm volatile("ldmatrix.sync.aligned.m8n8.x4.shared.b16 {%0,%1,%2,%3}, [%4];"
        : "=r"(r[0]), "=r"(r[1]), "=r"(r[2]), "=r"(r[3]) : "r"(addr));
}
__device__ __forceinline__ void hmma(float* c, const uint32_t* a, const uint32_t* b) {
    asm volatile("mma.sync.aligned.m16n8k16.row.col.f32.bf16.bf16.f32 "
        "{%0,%1,%2,%3}, {%4,%5,%6,%7}, {%8,%9}, {%0,%1,%2,%3};"
        : "+f"(c[0]), "+f"(c[1]), "+f"(c[2]), "+f"(c[3])
        : "r"(a[0]), "r"(a[1]), "r"(a[2]), "r"(a[3]), "r"(b[0]), "r"(b[1]));
}
__device__ __forceinline__ void cpa16(uint32_t dst, const void* src) {
    asm volatile("cp.async.cg.shared.global [%0], [%1], 16;" :: "r"(dst), "l"(src));
}
#define CP_COMMIT() asm volatile("cp.async.commit_group;" ::: "memory")
#define CP_WAIT(N)  asm volatile("cp.async.wait_group %0;" :: "n"(N) : "memory")

// ---------------------------------------------------------------------------
// fp32 -> (bf16 hi, bf16 lo) split, same layout. 4 elems/thread.
// ---------------------------------------------------------------------------
__global__ void cvt_hl(const float4* __restrict__ in, uint2* __restrict__ hi,
                       uint2* __restrict__ lo, int n4)
{
    int i = blockIdx.x * blockDim.x + threadIdx.x;
    if (i >= n4) return;
    float4 v = in[i];
    __nv_bfloat16 h0 = __float2bfloat16(v.x);
    __nv_bfloat16 h1 = __float2bfloat16(v.y);
    __nv_bfloat16 h2 = __float2bfloat16(v.z);
    __nv_bfloat16 h3 = __float2bfloat16(v.w);
    __nv_bfloat16 l0 = __float2bfloat16(v.x - __bfloat162float(h0));
    __nv_bfloat16 l1 = __float2bfloat16(v.y - __bfloat162float(h1));
    __nv_bfloat16 l2 = __float2bfloat16(v.z - __bfloat162float(h2));
    __nv_bfloat16 l3 = __float2bfloat16(v.w - __bfloat162float(h3));
    __nv_bfloat162 a = __halves2bfloat162(h0, h1), b = __halves2bfloat162(h2, h3);
    __nv_bfloat162 c = __halves2bfloat162(l0, l1), d = __halves2bfloat162(l2, l3);
    uint2 ho, lv;
    ho.x = *(uint32_t*)&a; ho.y = *(uint32_t*)&b;
    lv.x = *(uint32_t*)&c; lv.y = *(uint32_t*)&d;
    hi[i] = ho; lo[i] = lv;
}

// ---------------------------------------------------------------------------
// fp32 [K,N] -> transposed bf16 hi/lo [N,K]
// ---------------------------------------------------------------------------
__global__ void cvt_hl_t(const float* __restrict__ in, __nv_bfloat16* __restrict__ hi,
                         __nv_bfloat16* __restrict__ lo, int K, int N)
{
    __shared__ float t[32][33];
    const int n0 = blockIdx.x * 32, k0 = blockIdx.y * 32;
    const int tx = threadIdx.x, ty = threadIdx.y;
    #pragma unroll
    for (int j = ty; j < 32; j += 8)
        t[j][tx] = in[(size_t)(k0 + j) * N + n0 + tx];
    __syncthreads();
    #pragma unroll
    for (int j = ty; j < 32; j += 8) {
        float v = t[tx][j];                     // k_local = tx, n_local = j
        __nv_bfloat16 h = __float2bfloat16(v);
        __nv_bfloat16 l = __float2bfloat16(v - __bfloat162float(h));
        size_t o = (size_t)(n0 + j) * K + k0 + tx;
        hi[o] = h; lo[o] = l;
    }
}

// ---------------------------------------------------------------------------
// HMMA split-bf16 GEMM:  C[M,N] = A[M,K] @ B[N,K]^T + bias
//   BM=128, BN=128, BK=64; 256 threads (8 warps, 4x2); warp tile 32x64.
//   2-stage cp.async pipeline; SW128-style XOR swizzle; ldmatrix fragments.
//   3 HMMA per (frag, k-step): Ah*Bh + Ah*Bl + Al*Bh.
// ---------------------------------------------------------------------------
#define STAGE_BYTES 65536   // Ah 16K | Al 16K | Bh 16K | Bl 16K
#define GEMM_SMEM  (2*STAGE_BYTES)

__global__ __launch_bounds__(256, 1)
void gemm_mma(const __nv_bfloat16* __restrict__ Ah, const __nv_bfloat16* __restrict__ Al,
              const __nv_bfloat16* __restrict__ Bh, const __nv_bfloat16* __restrict__ Bl,
              const float* __restrict__ bias, float* __restrict__ C,
              int M, int N, int K)
{
    extern __shared__ char smem[];
    const uint32_t sb = smem_to_u32(smem);
    const int tid = threadIdx.x;
    const int wid = tid >> 5;
    const int lane = tid & 31;
    const int wm = wid >> 1;          // 0..3
    const int wn = wid & 1;           // 0..1
    const int row0 = blockIdx.y * 128;
    const int col0 = blockIdx.x * 128;

    const int ld_row = tid >> 3;      // 0..31
    const int ld_seg = tid & 7;       // 0..7

    float acc[2][8][4];
    #pragma unroll
    for (int a = 0; a < 2; ++a)
        #pragma unroll
        for (int b = 0; b < 8; ++b)
            #pragma unroll
            for (int c = 0; c < 4; ++c) acc[a][b][c] = 0.f;

    const int iters = K >> 6;

    // --- async tile loader ---
    auto issue = [&](int it, int stage) {
        const size_t kk = (size_t)(it << 6) + (ld_seg << 3);   // bf16 elems
        const uint32_t s0 = sb + stage * STAGE_BYTES;
        #pragma unroll
        for (int j = 0; j < 4; ++j) {
            const int row = ld_row + j * 32;
            uint32_t bo = (uint32_t)(row * 128 + ld_seg * 16);
            uint32_t sw = bo ^ ((bo >> 3) & 0x70);
            const size_t asrc = (size_t)(row0 + row) * K + kk;
            const size_t bsrc = (size_t)(col0 + row) * K + kk;
            cpa16(s0 + sw,          Ah + asrc);
            cpa16(s0 + 16384 + sw,  Al + asrc);
            cpa16(s0 + 32768 + sw,  Bh + bsrc);
            cpa16(s0 + 49152 + sw,  Bl + bsrc);
        }
        CP_COMMIT();
    };

    issue(0, 0);

    // per-thread ldmatrix address components
    const int sub = lane >> 3;        // matrix index 0..3
    const int rr  = lane & 7;
    // A: matrices {0:(m lo,k lo),1:(m hi,k lo),2:(m lo,k hi),3:(m hi,k hi)}
    const int arow[2] = { wm*32 + 0*16 + (sub & 1)*8 + rr,
                          wm*32 + 1*16 + (sub & 1)*8 + rr };
    const int acol = (sub >> 1) * 16;  // bytes
    // B: matrices {0:(n lo,k lo),1:(n lo,k hi),2:(n hi,k lo),3:(n hi,k hi)}
    const int brow[4] = { wn*64 + 0*16 + (sub >> 1)*8 + rr,
                          wn*64 + 1*16 + (sub >> 1)*8 + rr,
                          wn*64 + 2*16 + (sub >> 1)*8 + rr,
                          wn*64 + 3*16 + (sub >> 1)*8 + rr };
    const int bcol = (sub & 1) * 16;   // bytes

    for (int it = 0; it < iters; ++it) {
        const int stage = it & 1;
        if (it + 1 < iters) { issue(it + 1, stage ^ 1); CP_WAIT(1); }
        else                { CP_WAIT(0); }
        __syncthreads();

        const uint32_t sA_h = sb + stage * STAGE_BYTES;
        const uint32_t sA_l = sA_h + 16384;
        const uint32_t sB_h = sA_h + 32768;
        const uint32_t sB_l = sA_h + 49152;

        #pragma unroll
        for (int ks = 0; ks < 4; ++ks) {
            uint32_t ah[2][4], al[2][4], bh[4][4], bl[4][4];
            #pragma unroll
            for (int mi = 0; mi < 2; ++mi) {
                uint32_t off = (uint32_t)(arow[mi] * 128 +
                               ((ks*32 + acol) ^ ((arow[mi] & 7) << 4)));
                ldsm4(ah[mi], sA_h + off);
                ldsm4(al[mi], sA_l + off);
            }
            #pragma unroll
            for (int p = 0; p < 4; ++p) {
                uint32_t off = (uint32_t)(brow[p] * 128 +
                               ((ks*32 + bcol) ^ ((brow[p] & 7) << 4)));
                ldsm4(bh[p], sB_h + off);
                ldsm4(bl[p], sB_l + off);
            }
            #pragma unroll
            for (int mi = 0; mi < 2; ++mi)
                #pragma unroll
                for (int ni = 0; ni < 8; ++ni) {
                    const uint32_t* bhp = &bh[ni >> 1][(ni & 1) * 2];
                    const uint32_t* blp = &bl[ni >> 1][(ni & 1) * 2];
                    hmma(acc[mi][ni], ah[mi], bhp);
                    hmma(acc[mi][ni], ah[mi], blp);
                    hmma(acc[mi][ni], al[mi], bhp);
                }
        }
        __syncthreads();
    }

    // Epilogue
    const int g = lane >> 2, t = lane & 3;
    #pragma unroll
    for (int mi = 0; mi < 2; ++mi) {
        const int rlo = row0 + wm*32 + mi*16 + g;
        #pragma unroll
        for (int ni = 0; ni < 8; ++ni) {
            const int col = col0 + wn*64 + ni*8 + 2*t;
            const float b0 = bias[col], b1 = bias[col + 1];
            float2 lo = make_float2(acc[mi][ni][0] + b0, acc[mi][ni][1] + b1);
            float2 hi = make_float2(acc[mi][ni][2] + b0, acc[mi][ni][3] + b1);
            *(float2*)(C + (size_t)rlo * N + col)       = lo;
            *(float2*)(C + (size_t)(rlo + 8) * N + col) = hi;
        }
    }
}

// ---------------------------------------------------------------------------
// RoPE in-place (unchanged)
// ---------------------------------------------------------------------------
__global__ void rope_kernel(float* __restrict__ x, int nh, int total)
{
    int idx = blockIdx.x * blockDim.x + threadIdx.x;
    if (idx >= total) return;
    int d = idx & 63;
    int t = idx >> 6;
    int row = t / nh;
    int pos = row & (Sn - 1);

    float freq = __expf(-(2.0f * (float)d / 128.0f) * 9.210340371976184f);
    float ang = (float)pos * freq;
    float sv = sinf(ang);
    float cv = cosf(ang);

    float* p = x + (size_t)t * 128 + 2 * d;
    float xe = p[0], xo = p[1];
    p[0] = xe * cv - xo * sv;
    p[1] = xe * sv + xo * cv;
}

// ---------------------------------------------------------------------------
// Attention (unchanged from passing R1 kernel)
// ---------------------------------------------------------------------------
__global__ __launch_bounds__(256) void attn_kernel(
    const float* __restrict__ q, const float* __restrict__ k,
    const float* __restrict__ v, float* __restrict__ o)
{
    const int warp = threadIdx.x >> 5;
    const int lane = threadIdx.x & 31;
    const int i = blockIdx.x * 8 + warp;
    const int h = blockIdx.y;
    const int b = blockIdx.z;
    const int kvh = h >> 2;

    const float scale = 0.08838834764831845f;

    const size_t qoff = (((size_t)(b * Sn + i)) * NQ + h) * HD + lane * 4;
    float4 qv = *(const float4*)(q + qoff);
    qv.x *= scale; qv.y *= scale; qv.z *= scale; qv.w *= scale;

    int j0 = i - WINDOW; if (j0 < 0) j0 = 0;

    const float* kbase = k + ((size_t)b * Sn) * (NKV * HD) + kvh * HD + lane * 4;
    const float* vbase = v + ((size_t)b * Sn) * (NKV * HD) + kvh * HD + lane * 4;

    float m = -1e30f, l = 0.0f;
    float4 acc = make_float4(0.f, 0.f, 0.f, 0.f);

    for (int j = j0; j <= i; ++j) {
        float4 kv = *(const float4*)(kbase + (size_t)j * (NKV * HD));
        float s = qv.x * kv.x + qv.y * kv.y + qv.z * kv.z + qv.w * kv.w;
        s += __shfl_xor_sync(0xffffffffu, s, 16);
        s += __shfl_xor_sync(0xffffffffu, s, 8);
        s += __shfl_xor_sync(0xffffffffu, s, 4);
        s += __shfl_xor_sync(0xffffffffu, s, 2);
        s += __shfl_xor_sync(0xffffffffu, s, 1);

        float4 vv = *(const float4*)(vbase + (size_t)j * (NKV * HD));
        float mn = fmaxf(m, s);
        float corr = __expf(m - mn);
        float p = __expf(s - mn);
        l = l * corr + p;
        acc.x = acc.x * corr + p * vv.x;
        acc.y = acc.y * corr + p * vv.y;
        acc.z = acc.z * corr + p * vv.z;
        acc.w = acc.w * corr + p * vv.w;
        m = mn;
    }

    float inv = 1.0f / l;
    float4 r = make_float4(acc.x * inv, acc.y * inv, acc.z * inv, acc.w * inv);
    *(float4*)(o + qoff) = r;
}

// ---------------------------------------------------------------------------
extern "C" void kernel_launch(void* const* d_in, const int* in_sizes, int n_in,
                              void* d_out, int out_size)
{
    const float* x  = (const float*)d_in[0];
    const float* Wq = (const float*)d_in[1];
    const float* bq = (const float*)d_in[2];
    const float* Wk = (const float*)d_in[3];
    const float* bk = (const float*)d_in[4];
    const float* Wv = (const float*)d_in[5];
    const float* bv = (const float*)d_in[6];
    const float* Wo = (const float*)d_in[7];
    const float* bo = (const float*)d_in[8];
    float* out = (float*)d_out;

    float *qp, *kp, *vp, *ap;
    cudaGetSymbolAddress((void**)&qp, g_q);
    cudaGetSymbolAddress((void**)&kp, g_k);
    cudaGetSymbolAddress((void**)&vp, g_v);
    cudaGetSymbolAddress((void**)&ap, g_attn);
    __nv_bfloat16 *xh, *xl, *ah, *al, *wqh, *wql, *wkh, *wkl, *wvh, *wvl, *woh, *wol;
    cudaGetSymbolAddress((void**)&xh, g_xh);   cudaGetSymbolAddress((void**)&xl, g_xl);
    cudaGetSymbolAddress((void**)&ah, g_ah);   cudaGetSymbolAddress((void**)&al, g_al);
    cudaGetSymbolAddress((void**)&wqh, g_wqh); cudaGetSymbolAddress((void**)&wql, g_wql);
    cudaGetSymbolAddress((void**)&wkh, g_wkh); cudaGetSymbolAddress((void**)&wkl, g_wkl);
    cudaGetSymbolAddress((void**)&wvh, g_wvh); cudaGetSymbolAddress((void**)&wvl, g_wvl);
    cudaGetSymbolAddress((void**)&woh, g_woh); cudaGetSymbolAddress((void**)&wol, g_wol);

    cudaFuncSetAttribute(gemm_mma, cudaFuncAttributeMaxDynamicSharedMemorySize, GEMM_SMEM);

    // Split-convert activations and (transposed) weights
    const int n4x = Mrows * En / 4;   // 2097152
    cvt_hl<<<n4x / 1024, 1024>>>((const float4*)x, (uint2*)xh, (uint2*)xl, n4x);
    dim3 tb(32, 8);
    cvt_hl_t<<<dim3(64, 64), tb>>>(Wq, wqh, wql, 2048, 2048);
    cvt_hl_t<<<dim3(16, 64), tb>>>(Wk, wkh, wkl, 2048, 512);
    cvt_hl_t<<<dim3(16, 64), tb>>>(Wv, wvh, wvl, 2048, 512);
    cvt_hl_t<<<dim3(64, 64), tb>>>(Wo, woh, wol, 2048, 2048);

    // QKV projections on tensor cores (HMMA)
    gemm_mma<<<dim3(2048/128, Mrows/128), 256, GEMM_SMEM>>>(xh, xl, wqh, wql, bq, qp, Mrows, 2048, En);
    gemm_mma<<<dim3(512/128,  Mrows/128), 256, GEMM_SMEM>>>(xh, xl, wkh, wkl, bk, kp, Mrows, 512, En);
    gemm_mma<<<dim3(512/128,  Mrows/128), 256, GEMM_SMEM>>>(xh, xl, wvh, wvl, bv, vp, Mrows, 512, En);

    // RoPE on q and k
    {
        int totq = Mrows * NQ * 64;
        rope_kernel<<<(totq + 255) / 256, 256>>>(qp, NQ, totq);
        int totk = Mrows * NKV * 64;
        rope_kernel<<<(totk + 255) / 256, 256>>>(kp, NKV, totk);
    }

    // Attention
    {
        dim3 grid(Sn / 8, NQ, Bn);
        attn_kernel<<<grid, 256>>>(qp, kp, vp, ap);
    }

    // Output projection
    cvt_hl<<<n4x / 1024, 1024>>>((const float4*)ap, (uint2*)ah, (uint2*)al, n4x);
    gemm_mma<<<dim3(2048/128, Mrows/128), 256, GEMM_SMEM>>>(ah, al, woh, wol, bo, out, Mrows, 2048, En);
}

// round 4
// speedup vs baseline: 4.3544x; 2.4504x over previous
#include <cuda_runtime.h>
#include <cuda_bf16.h>
#include <math.h>
#include <cstdint>

// Problem constants
#define Bn 2
#define Sn 2048
#define En 2048
#define NQ 16
#define NKV 4
#define HD 128
#define WINDOW 512
#define Mrows (Bn*Sn)          // 4096

// ---------------------------------------------------------------------------
// Scratch (device globals; no allocation allowed)
// ---------------------------------------------------------------------------
__device__ float g_q[(size_t)Mrows * NQ * HD];     // fp32 q (pre-rope)
__device__ float g_k[(size_t)Mrows * NKV * HD];
__device__ float g_v[(size_t)Mrows * NKV * HD];

// split-bf16 activations
__device__ __nv_bfloat16 g_xh[(size_t)Mrows * En];
__device__ __nv_bfloat16 g_xl[(size_t)Mrows * En];
__device__ __nv_bfloat16 g_ah[(size_t)Mrows * En];   // attention out hi
__device__ __nv_bfloat16 g_al[(size_t)Mrows * En];   // attention out lo
// rope'd+split q/k, split v
__device__ __nv_bfloat16 g_qhb[(size_t)Mrows * NQ * HD];
__device__ __nv_bfloat16 g_qlb[(size_t)Mrows * NQ * HD];
__device__ __nv_bfloat16 g_khb[(size_t)Mrows * NKV * HD];
__device__ __nv_bfloat16 g_klb[(size_t)Mrows * NKV * HD];
__device__ __nv_bfloat16 g_vhb[(size_t)Mrows * NKV * HD];
__device__ __nv_bfloat16 g_vlb[(size_t)Mrows * NKV * HD];
// weights, transposed to [N, K]
__device__ __nv_bfloat16 g_wqh[(size_t)2048 * 2048];
__device__ __nv_bfloat16 g_wql[(size_t)2048 * 2048];
__device__ __nv_bfloat16 g_wkh[(size_t)512 * 2048];
__device__ __nv_bfloat16 g_wkl[(size_t)512 * 2048];
__device__ __nv_bfloat16 g_wvh[(size_t)512 * 2048];
__device__ __nv_bfloat16 g_wvl[(size_t)512 * 2048];
__device__ __nv_bfloat16 g_woh[(size_t)2048 * 2048];
__device__ __nv_bfloat16 g_wol[(size_t)2048 * 2048];

// ---------------------------------------------------------------------------
// PTX helpers (base sm_103: mma.sync / ldmatrix / cp.async)
// ---------------------------------------------------------------------------
__device__ __forceinline__ uint32_t smem_to_u32(const void* p) {
    uint32_t a;
    asm("{ .reg .u64 t; cvta.to.shared.u64 t, %1; cvt.u32.u64 %0, t; }" : "=r"(a) : "l"(p));
    return a;
}
__device__ __forceinline__ void ldsm4(uint32_t* r, uint32_t addr) {
    asm volatile("ldmatrix.sync.aligned.m8n8.x4.shared.b16 {%0,%1,%2,%3}, [%4];"
        : "=r"(r[0]), "=r"(r[1]), "=r"(r[2]), "=r"(r[3]) : "r"(addr));
}
__device__ __forceinline__ void ldsm4t(uint32_t* r, uint32_t addr) {
    asm volatile("ldmatrix.sync.aligned.m8n8.x4.trans.shared.b16 {%0,%1,%2,%3}, [%4];"
        : "=r"(r[0]), "=r"(r[1]), "=r"(r[2]), "=r"(r[3]) : "r"(addr));
}
__device__ __forceinline__ void hmma(float* c, const uint32_t* a, const uint32_t* b) {
    asm volatile("mma.sync.aligned.m16n8k16.row.col.f32.bf16.bf16.f32 "
        "{%0,%1,%2,%3}, {%4,%5,%6,%7}, {%8,%9}, {%0,%1,%2,%3};"
        : "+f"(c[0]), "+f"(c[1]), "+f"(c[2]), "+f"(c[3])
        : "r"(a[0]), "r"(a[1]), "r"(a[2]), "r"(a[3]), "r"(b[0]), "r"(b[1]));
}
__device__ __forceinline__ void cpa16(uint32_t dst, const void* src) {
    asm volatile("cp.async.cg.shared.global [%0], [%1], 16;" :: "r"(dst), "l"(src));
}
#define CP_COMMIT() asm volatile("cp.async.commit_group;" ::: "memory")
#define CP_WAIT(N)  asm volatile("cp.async.wait_group %0;" :: "n"(N) : "memory")

__device__ __forceinline__ uint32_t pack_bf16(__nv_bfloat16 a, __nv_bfloat16 b) {
    __nv_bfloat162 v = __halves2bfloat162(a, b);
    return *(uint32_t*)&v;
}
// split float pair -> (hi u32, lo u32)
__device__ __forceinline__ void split_pair(float a, float b, uint32_t& hi, uint32_t& lo) {
    __nv_bfloat16 h0 = __float2bfloat16(a), h1 = __float2bfloat16(b);
    __nv_bfloat16 l0 = __float2bfloat16(a - __bfloat162float(h0));
    __nv_bfloat16 l1 = __float2bfloat16(b - __bfloat162float(h1));
    hi = pack_bf16(h0, h1); lo = pack_bf16(l0, l1);
}

// ---------------------------------------------------------------------------
// fp32 -> (bf16 hi, bf16 lo), 4 elems/thread.
// ---------------------------------------------------------------------------
__global__ void cvt_hl(const float4* __restrict__ in, uint2* __restrict__ hi,
                       uint2* __restrict__ lo, int n4)
{
    int i = blockIdx.x * blockDim.x + threadIdx.x;
    if (i >= n4) return;
    float4 v = in[i];
    uint2 ho, lv;
    split_pair(v.x, v.y, ho.x, lv.x);
    split_pair(v.z, v.w, ho.y, lv.y);
    hi[i] = ho; lo[i] = lv;
}

// ---------------------------------------------------------------------------
// fp32 [K,N] -> transposed bf16 hi/lo [N,K]
// ---------------------------------------------------------------------------
__global__ void cvt_hl_t(const float* __restrict__ in, __nv_bfloat16* __restrict__ hi,
                         __nv_bfloat16* __restrict__ lo, int K, int N)
{
    __shared__ float t[32][33];
    const int n0 = blockIdx.x * 32, k0 = blockIdx.y * 32;
    const int tx = threadIdx.x, ty = threadIdx.y;
    #pragma unroll
    for (int j = ty; j < 32; j += 8)
        t[j][tx] = in[(size_t)(k0 + j) * N + n0 + tx];
    __syncthreads();
    #pragma unroll
    for (int j = ty; j < 32; j += 8) {
        float v = t[tx][j];
        __nv_bfloat16 h = __float2bfloat16(v);
        __nv_bfloat16 l = __float2bfloat16(v - __bfloat162float(h));
        size_t o = (size_t)(n0 + j) * K + k0 + tx;
        hi[o] = h; lo[o] = l;
    }
}

// ---------------------------------------------------------------------------
// RoPE + scale + bf16 hi/lo split.  x fp32 [rows, nh, 128] -> xh/xl same layout.
// ---------------------------------------------------------------------------
__global__ void rope_split(const float* __restrict__ x, __nv_bfloat16* __restrict__ xh,
                           __nv_bfloat16* __restrict__ xl, int nh, int total, float scale)
{
    int idx = blockIdx.x * blockDim.x + threadIdx.x;
    if (idx >= total) return;
    int d = idx & 63;
    int t = idx >> 6;
    int row = t / nh;
    int pos = row & (Sn - 1);

    float freq = __expf(-(2.0f * (float)d / 128.0f) * 9.210340371976184f);
    float ang = (float)pos * freq;
    float sv = sinf(ang), cv = cosf(ang);

    const float* p = x + (size_t)t * 128 + 2 * d;
    float xe = p[0], xo = p[1];
    float r0 = (xe * cv - xo * sv) * scale;
    float r1 = (xe * sv + xo * cv) * scale;
    uint32_t hi, lo;
    split_pair(r0, r1, hi, lo);
    ((uint32_t*)xh)[(size_t)t * 64 + d] = hi;
    ((uint32_t*)xl)[(size_t)t * 64 + d] = lo;
}

// ---------------------------------------------------------------------------
// HMMA split-bf16 GEMM (unchanged from R3):  C = A[M,K] @ B[N,K]^T + bias
// ---------------------------------------------------------------------------
#define STAGE_BYTES 65536
#define GEMM_SMEM  (2*STAGE_BYTES)

__global__ __launch_bounds__(256, 1)
void gemm_mma(const __nv_bfloat16* __restrict__ Ah, const __nv_bfloat16* __restrict__ Al,
              const __nv_bfloat16* __restrict__ Bh, const __nv_bfloat16* __restrict__ Bl,
              const float* __restrict__ bias, float* __restrict__ C,
              int M, int N, int K)
{
    extern __shared__ char smem[];
    const uint32_t sb = smem_to_u32(smem);
    const int tid = threadIdx.x;
    const int wid = tid >> 5;
    const int lane = tid & 31;
    const int wm = wid >> 1;
    const int wn = wid & 1;
    const int row0 = blockIdx.y * 128;
    const int col0 = blockIdx.x * 128;

    const int ld_row = tid >> 3;
    const int ld_seg = tid & 7;

    float acc[2][8][4];
    #pragma unroll
    for (int a = 0; a < 2; ++a)
        #pragma unroll
        for (int b = 0; b < 8; ++b)
            #pragma unroll
            for (int c = 0; c < 4; ++c) acc[a][b][c] = 0.f;

    const int iters = K >> 6;

    auto issue = [&](int it, int stage) {
        const size_t kk = (size_t)(it << 6) + (ld_seg << 3);
        const uint32_t s0 = sb + stage * STAGE_BYTES;
        #pragma unroll
        for (int j = 0; j < 4; ++j) {
            const int row = ld_row + j * 32;
            uint32_t bo = (uint32_t)(row * 128 + ld_seg * 16);
            uint32_t sw = bo ^ ((bo >> 3) & 0x70);
            const size_t asrc = (size_t)(row0 + row) * K + kk;
            const size_t bsrc = (size_t)(col0 + row) * K + kk;
            cpa16(s0 + sw,          Ah + asrc);
            cpa16(s0 + 16384 + sw,  Al + asrc);
            cpa16(s0 + 32768 + sw,  Bh + bsrc);
            cpa16(s0 + 49152 + sw,  Bl + bsrc);
        }
        CP_COMMIT();
    };

    issue(0, 0);

    const int sub = lane >> 3;
    const int rr  = lane & 7;
    const int arow[2] = { wm*32 + 0*16 + (sub & 1)*8 + rr,
                          wm*32 + 1*16 + (sub & 1)*8 + rr };
    const int acol = (sub >> 1) * 16;
    const int brow[4] = { wn*64 + 0*16 + (sub >> 1)*8 + rr,
                          wn*64 + 1*16 + (sub >> 1)*8 + rr,
                          wn*64 + 2*16 + (sub >> 1)*8 + rr,
                          wn*64 + 3*16 + (sub >> 1)*8 + rr };
    const int bcol = (sub & 1) * 16;

    for (int it = 0; it < iters; ++it) {
        const int stage = it & 1;
        if (it + 1 < iters) { issue(it + 1, stage ^ 1); CP_WAIT(1); }
        else                { CP_WAIT(0); }
        __syncthreads();

        const uint32_t sA_h = sb + stage * STAGE_BYTES;
        const uint32_t sA_l = sA_h + 16384;
        const uint32_t sB_h = sA_h + 32768;
        const uint32_t sB_l = sA_h + 49152;

        #pragma unroll
        for (int ks = 0; ks < 4; ++ks) {
            uint32_t ah[2][4], al[2][4], bh[4][4], bl[4][4];
            #pragma unroll
            for (int mi = 0; mi < 2; ++mi) {
                uint32_t off = (uint32_t)(arow[mi] * 128 +
                               ((ks*32 + acol) ^ ((arow[mi] & 7) << 4)));
                ldsm4(ah[mi], sA_h + off);
                ldsm4(al[mi], sA_l + off);
            }
            #pragma unroll
            for (int p = 0; p < 4; ++p) {
                uint32_t off = (uint32_t)(brow[p] * 128 +
                               ((ks*32 + bcol) ^ ((brow[p] & 7) << 4)));
                ldsm4(bh[p], sB_h + off);
                ldsm4(bl[p], sB_l + off);
            }
            #pragma unroll
            for (int mi = 0; mi < 2; ++mi)
                #pragma unroll
                for (int ni = 0; ni < 8; ++ni) {
                    const uint32_t* bhp = &bh[ni >> 1][(ni & 1) * 2];
                    const uint32_t* blp = &bl[ni >> 1][(ni & 1) * 2];
                    hmma(acc[mi][ni], ah[mi], bhp);
                    hmma(acc[mi][ni], ah[mi], blp);
                    hmma(acc[mi][ni], al[mi], bhp);
                }
        }
        __syncthreads();
    }

    const int g = lane >> 2, t = lane & 3;
    #pragma unroll
    for (int mi = 0; mi < 2; ++mi) {
        const int rlo = row0 + wm*32 + mi*16 + g;
        #pragma unroll
        for (int ni = 0; ni < 8; ++ni) {
            const int col = col0 + wn*64 + ni*8 + 2*t;
            const float b0 = bias[col], b1 = bias[col + 1];
            float2 lo = make_float2(acc[mi][ni][0] + b0, acc[mi][ni][1] + b1);
            float2 hi = make_float2(acc[mi][ni][2] + b0, acc[mi][ni][3] + b1);
            *(float2*)(C + (size_t)rlo * N + col)       = lo;
            *(float2*)(C + (size_t)(rlo + 8) * N + col) = hi;
        }
    }
}

// ---------------------------------------------------------------------------
// Flash attention on HMMA, split-bf16 for QK^T and P*V.
//   Block: (q-tile 64, h, b). 4 warps, each 16 q rows. j-tiles of 64.
// SMEM map (bytes):
//   Qh 0, Ql 17408                                 (64 rows x 272B)
//   KV buf{0,1} at 34816 + buf*69632: Kh,Kl,Vh,Vl  (each 17408)
//   Ph 174080, Pl 183296                           (64 rows x 144B)
// total 192512
// ---------------------------------------------------------------------------
#define ATT_SMEM 192512

__global__ __launch_bounds__(128, 1)
void attn_mma(const __nv_bfloat16* __restrict__ qh, const __nv_bfloat16* __restrict__ ql,
              const __nv_bfloat16* __restrict__ kh, const __nv_bfloat16* __restrict__ kl,
              const __nv_bfloat16* __restrict__ vh, const __nv_bfloat16* __restrict__ vl,
              __nv_bfloat16* __restrict__ oh, __nv_bfloat16* __restrict__ ol)
{
    extern __shared__ char smem[];
    const uint32_t sb = smem_to_u32(smem);
    const int tid = threadIdx.x, lane = tid & 31, wq = tid >> 5;
    const int i0 = blockIdx.x * 64;
    const int h  = blockIdx.y, b = blockIdx.z, kvh = h >> 2;

    // stage Q (once)
    for (int c = tid; c < 1024; c += 128) {
        int r = c >> 4, ch = c & 15;
        uint32_t dst = sb + r * 272 + ch * 16;
        size_t src = (((size_t)(b * Sn + i0 + r) * NQ + h) * 128) + ch * 8;
        cpa16(dst,         qh + src);
        cpa16(dst + 17408, ql + src);
    }
    CP_COMMIT();

    int jt0 = i0 - WINDOW; if (jt0 < 0) jt0 = 0;
    const int ntiles = (i0 - jt0) / 64 + 1;

    auto stage_kv = [&](int t, int buf) {
        int jt = jt0 + t * 64;
        uint32_t s0 = sb + 34816 + buf * 69632;
        for (int c = tid; c < 1024; c += 128) {
            int r = c >> 4, ch = c & 15;
            uint32_t dst = s0 + r * 272 + ch * 16;
            size_t src = (((size_t)(b * Sn + jt + r) * NKV + kvh) * 128) + ch * 8;
            cpa16(dst,         kh + src);
            cpa16(dst + 17408, kl + src);
            cpa16(dst + 34816, vh + src);
            cpa16(dst + 52224, vl + src);
        }
        CP_COMMIT();
    };

    stage_kv(0, 0);

    const int g = lane >> 2, t4 = lane & 3;
    const int a_r  = ((lane >> 3) & 1) * 8 + (lane & 7);
    const int a_c8 = (lane >> 4) & 1;

    float m_r[2] = {-1e30f, -1e30f};
    float l_r[2] = {0.f, 0.f};
    float o_acc[16][4];
    #pragma unroll
    for (int nb = 0; nb < 16; ++nb)
        #pragma unroll
        for (int c = 0; c < 4; ++c) o_acc[nb][c] = 0.f;

    const uint32_t sPh = sb + 174080, sPl = sb + 183296;

    for (int t = 0; t < ntiles; ++t) {
        const int buf = t & 1;
        if (t + 1 < ntiles) { stage_kv(t + 1, buf ^ 1); CP_WAIT(1); }
        else                { CP_WAIT(0); }
        __syncthreads();

        const uint32_t sQh = sb, sQl = sb + 17408;
        const uint32_t sKh = sb + 34816 + buf * 69632;
        const uint32_t sKl = sKh + 17408;
        const uint32_t sVh = sKh + 34816;
        const uint32_t sVl = sKh + 52224;

        // ---- S = (Qh+Ql)(Kh+Kl)^T (3-term split), 16x64 per warp ----
        float s_c[8][4];
        #pragma unroll
        for (int nb = 0; nb < 8; ++nb)
            #pragma unroll
            for (int c = 0; c < 4; ++c) s_c[nb][c] = 0.f;

        #pragma unroll
        for (int ks = 0; ks < 8; ++ks) {
            uint32_t ah[4], al[4];
            uint32_t qoff = (uint32_t)((wq * 16 + a_r) * 272 + (ks * 16 + a_c8 * 8) * 2);
            ldsm4(ah, sQh + qoff);
            ldsm4(al, sQl + qoff);
            #pragma unroll
            for (int p = 0; p < 4; ++p) {
                uint32_t bh[4], bl[4];
                uint32_t koff = (uint32_t)((p * 16 + a_r) * 272 + (ks * 16 + a_c8 * 8) * 2);
                ldsm4(bh, sKh + koff);
                ldsm4(bl, sKl + koff);
                uint32_t bh0[2] = {bh[0], bh[2]}, bh1[2] = {bh[1], bh[3]};
                uint32_t bl0[2] = {bl[0], bl[2]}, bl1[2] = {bl[1], bl[3]};
                hmma(s_c[2*p],   ah, bh0);
                hmma(s_c[2*p+1], ah, bh1);
                hmma(s_c[2*p],   ah, bl0);
                hmma(s_c[2*p+1], ah, bl1);
                hmma(s_c[2*p],   al, bh0);
                hmma(s_c[2*p+1], al, bh1);
            }
        }

        // ---- mask + online softmax ----
        const int jt = jt0 + t * 64;
        float mt[2] = {-1e30f, -1e30f};
        #pragma unroll
        for (int nb = 0; nb < 8; ++nb) {
            const int jbase = jt + nb * 8 + t4 * 2;
            #pragma unroll
            for (int c = 0; c < 4; ++c) {
                const int rr = c >> 1;
                const int i = i0 + wq * 16 + g + rr * 8;
                const int j = jbase + (c & 1);
                if (!((j <= i) && (i - j <= WINDOW)))
                    s_c[nb][c] = -1e30f;
                mt[rr] = fmaxf(mt[rr], s_c[nb][c]);
            }
        }
        float corr[2];
        #pragma unroll
        for (int rr = 0; rr < 2; ++rr) {
            mt[rr] = fmaxf(mt[rr], __shfl_xor_sync(0xffffffffu, mt[rr], 1));
            mt[rr] = fmaxf(mt[rr], __shfl_xor_sync(0xffffffffu, mt[rr], 2));
            float mn = fmaxf(m_r[rr], mt[rr]);
            corr[rr] = __expf(m_r[rr] - mn);
            m_r[rr] = mn;
        }
        float ps[2] = {0.f, 0.f};
        #pragma unroll
        for (int nb = 0; nb < 8; ++nb) {
            #pragma unroll
            for (int c = 0; c < 4; ++c) {
                const int rr = c >> 1;
                float p = __expf(s_c[nb][c] - m_r[rr]);
                s_c[nb][c] = p;
                ps[rr] += p;
            }
        }
        #pragma unroll
        for (int rr = 0; rr < 2; ++rr) {
            ps[rr] += __shfl_xor_sync(0xffffffffu, ps[rr], 1);
            ps[rr] += __shfl_xor_sync(0xffffffffu, ps[rr], 2);
            l_r[rr] = l_r[rr] * corr[rr] + ps[rr];
        }
        #pragma unroll
        for (int nb = 0; nb < 16; ++nb) {
            o_acc[nb][0] *= corr[0]; o_acc[nb][1] *= corr[0];
            o_acc[nb][2] *= corr[1]; o_acc[nb][3] *= corr[1];
        }

        // ---- P -> smem (bf16 hi/lo) ----
        #pragma unroll
        for (int nb = 0; nb < 8; ++nb) {
            #pragma unroll
            for (int rr = 0; rr < 2; ++rr) {
                uint32_t hi, lo;
                split_pair(s_c[nb][rr*2], s_c[nb][rr*2+1], hi, lo);
                const int row = wq * 16 + g + rr * 8;
                uint32_t off = (uint32_t)(row * 144 + (nb * 8 + t4 * 2) * 2);
                *(uint32_t*)(smem + (174080 - 0) + off - 0 + 0) = 0; // placeholder avoided
                asm volatile("st.shared.b32 [%0], %1;" :: "r"(sPh + off), "r"(hi) : "memory");
                asm volatile("st.shared.b32 [%0], %1;" :: "r"(sPl + off), "r"(lo) : "memory");
            }
        }
        __syncwarp();

        // ---- O += (Ph+Pl) * (Vh+Vl)  (3-term split) ----
        #pragma unroll
        for (int ks = 0; ks < 4; ++ks) {
            uint32_t aph[4], apl[4];
            uint32_t poff = (uint32_t)((wq * 16 + a_r) * 144 + (ks * 16 + a_c8 * 8) * 2);
            ldsm4(aph, sPh + poff);
            ldsm4(apl, sPl + poff);
            #pragma unroll
            for (int p2 = 0; p2 < 8; ++p2) {
                uint32_t bvh[4], bvl[4];
                uint32_t voff = (uint32_t)((ks * 16 + a_r) * 272 + (p2 * 16 + a_c8 * 8) * 2);
                ldsm4t(bvh, sVh + voff);
                ldsm4t(bvl, sVl + voff);
                uint32_t bh0[2] = {bvh[0], bvh[1]}, bh1[2] = {bvh[2], bvh[3]};
                uint32_t bl0[2] = {bvl[0], bvl[1]}, bl1[2] = {bvl[2], bvl[3]};
                hmma(o_acc[2*p2],   aph, bh0);
                hmma(o_acc[2*p2+1], aph, bh1);
                hmma(o_acc[2*p2],   apl, bh0);
                hmma(o_acc[2*p2+1], apl, bh1);
                hmma(o_acc[2*p2],   aph, bl0);
                hmma(o_acc[2*p2+1], aph, bl1);
            }
        }
        __syncthreads();
    }

    // ---- epilogue: normalize, split to bf16 hi/lo, write ----
    const float inv0 = 1.0f / l_r[0], inv1 = 1.0f / l_r[1];
    #pragma unroll
    for (int nb = 0; nb < 16; ++nb) {
        const int d = nb * 8 + t4 * 2;
        #pragma unroll
        for (int rr = 0; rr < 2; ++rr) {
            const int i = i0 + wq * 16 + g + rr * 8;
            const float inv = rr ? inv1 : inv0;
            uint32_t hi, lo;
            split_pair(o_acc[nb][rr*2] * inv, o_acc[nb][rr*2+1] * inv, hi, lo);
            const size_t o32 = ((size_t)(b * Sn + i) * NQ + h) * 64 + (d >> 1);
            ((uint32_t*)oh)[o32] = hi;
            ((uint32_t*)ol)[o32] = lo;
        }
    }
}

// ---------------------------------------------------------------------------
extern "C" void kernel_launch(void* const* d_in, const int* in_sizes, int n_in,
                              void* d_out, int out_size)
{
    const float* x  = (const float*)d_in[0];
    const float* Wq = (const float*)d_in[1];
    const float* bq = (const float*)d_in[2];
    const float* Wk = (const float*)d_in[3];
    const float* bk = (const float*)d_in[4];
    const float* Wv = (const float*)d_in[5];
    const float* bv = (const float*)d_in[6];
    const float* Wo = (const float*)d_in[7];
    const float* bo = (const float*)d_in[8];
    float* out = (float*)d_out;

    float *qp, *kp, *vp;
    cudaGetSymbolAddress((void**)&qp, g_q);
    cudaGetSymbolAddress((void**)&kp, g_k);
    cudaGetSymbolAddress((void**)&vp, g_v);
    __nv_bfloat16 *xh, *xl, *ah, *al;
    __nv_bfloat16 *qhb, *qlb, *khb, *klb, *vhb, *vlb;
    __nv_bfloat16 *wqh, *wql, *wkh, *wkl, *wvh, *wvl, *woh, *wol;
    cudaGetSymbolAddress((void**)&xh, g_xh);   cudaGetSymbolAddress((void**)&xl, g_xl);
    cudaGetSymbolAddress((void**)&ah, g_ah);   cudaGetSymbolAddress((void**)&al, g_al);
    cudaGetSymbolAddress((void**)&qhb, g_qhb); cudaGetSymbolAddress((void**)&qlb, g_qlb);
    cudaGetSymbolAddress((void**)&khb, g_khb); cudaGetSymbolAddress((void**)&klb, g_klb);
    cudaGetSymbolAddress((void**)&vhb, g_vhb); cudaGetSymbolAddress((void**)&vlb, g_vlb);
    cudaGetSymbolAddress((void**)&wqh, g_wqh); cudaGetSymbolAddress((void**)&wql, g_wql);
    cudaGetSymbolAddress((void**)&wkh, g_wkh); cudaGetSymbolAddress((void**)&wkl, g_wkl);
    cudaGetSymbolAddress((void**)&wvh, g_wvh); cudaGetSymbolAddress((void**)&wvl, g_wvl);
    cudaGetSymbolAddress((void**)&woh, g_woh); cudaGetSymbolAddress((void**)&wol, g_wol);

    cudaFuncSetAttribute(gemm_mma, cudaFuncAttributeMaxDynamicSharedMemorySize, GEMM_SMEM);
    cudaFuncSetAttribute(attn_mma, cudaFuncAttributeMaxDynamicSharedMemorySize, ATT_SMEM);

    // Split-convert activations and (transposed) weights
    const int n4x = Mrows * En / 4;
    cvt_hl<<<n4x / 1024, 1024>>>((const float4*)x, (uint2*)xh, (uint2*)xl, n4x);
    dim3 tb(32, 8);
    cvt_hl_t<<<dim3(64, 64), tb>>>(Wq, wqh, wql, 2048, 2048);
    cvt_hl_t<<<dim3(16, 64), tb>>>(Wk, wkh, wkl, 2048, 512);
    cvt_hl_t<<<dim3(16, 64), tb>>>(Wv, wvh, wvl, 2048, 512);
    cvt_hl_t<<<dim3(64, 64), tb>>>(Wo, woh, wol, 2048, 2048);

    // QKV projections (HMMA)
    gemm_mma<<<dim3(2048/128, Mrows/128), 256, GEMM_SMEM>>>(xh, xl, wqh, wql, bq, qp, Mrows, 2048, En);
    gemm_mma<<<dim3(512/128,  Mrows/128), 256, GEMM_SMEM>>>(xh, xl, wkh, wkl, bk, kp, Mrows, 512, En);
    gemm_mma<<<dim3(512/128,  Mrows/128), 256, GEMM_SMEM>>>(xh, xl, wvh, wvl, bv, vp, Mrows, 512, En);

    // RoPE + split (q scaled by 1/sqrt(HD)), v split
    {
        int totq = Mrows * NQ * 64;
        rope_split<<<(totq + 255) / 256, 256>>>(qp, qhb, qlb, NQ, totq, 0.08838834764831845f);
        int totk = Mrows * NKV * 64;
        rope_split<<<(totk + 255) / 256, 256>>>(kp, khb, klb, NKV, totk, 1.0f);
        int n4v = Mrows * NKV * HD / 4;
        cvt_hl<<<(n4v + 1023) / 1024, 1024>>>((const float4*)vp, (uint2*)vhb, (uint2*)vlb, n4v);
    }

    // Flash attention (HMMA), writes split-bf16 output directly
    attn_mma<<<dim3(Sn/64, NQ, Bn), 128, ATT_SMEM>>>(qhb, qlb, khb, klb, vhb, vlb, ah, al);

    // Output projection
    gemm_mma<<<dim3(2048/128, Mrows/128), 256, GEMM_SMEM>>>(ah, al, woh, wol, bo, out, Mrows, 2048, En);
}

// round 5
// speedup vs baseline: 7.9797x; 1.8325x over previous
#include <cuda_runtime.h>
#include <cuda_bf16.h>
#include <cuda_fp16.h>
#include <math.h>
#include <cstdint>

// Problem constants
#define Bn 2
#define Sn 2048
#define En 2048
#define NQ 16
#define NKV 4
#define HD 128
#define WINDOW 512
#define Mrows (Bn*Sn)          // 4096

// ---------------------------------------------------------------------------
// Scratch (device globals; no allocation allowed)
// ---------------------------------------------------------------------------
__device__ float g_q[(size_t)Mrows * NQ * HD];     // fp32 q (pre-rope)
__device__ float g_k[(size_t)Mrows * NKV * HD];
__device__ float g_v[(size_t)Mrows * NKV * HD];

// fp16 activations / weights (single precision term for GEMMs)
__device__ __half g_xf[(size_t)Mrows * En];
__device__ __half g_of[(size_t)Mrows * En];        // attention out, fp16
__device__ __half g_wq[(size_t)2048 * 2048];       // [N,K]
__device__ __half g_wk[(size_t)512 * 2048];
__device__ __half g_wv[(size_t)512 * 2048];
__device__ __half g_wo[(size_t)2048 * 2048];

// rope'd+split q/k, split v (bf16 hi/lo for high-precision attention)
__device__ __nv_bfloat16 g_qhb[(size_t)Mrows * NQ * HD];
__device__ __nv_bfloat16 g_qlb[(size_t)Mrows * NQ * HD];
__device__ __nv_bfloat16 g_khb[(size_t)Mrows * NKV * HD];
__device__ __nv_bfloat16 g_klb[(size_t)Mrows * NKV * HD];
__device__ __nv_bfloat16 g_vhb[(size_t)Mrows * NKV * HD];
__device__ __nv_bfloat16 g_vlb[(size_t)Mrows * NKV * HD];

// ---------------------------------------------------------------------------
// PTX helpers (base sm_103: mma.sync / ldmatrix / cp.async)
// ---------------------------------------------------------------------------
__device__ __forceinline__ uint32_t smem_to_u32(const void* p) {
    uint32_t a;
    asm("{ .reg .u64 t; cvta.to.shared.u64 t, %1; cvt.u32.u64 %0, t; }" : "=r"(a) : "l"(p));
    return a;
}
__device__ __forceinline__ void ldsm4(uint32_t* r, uint32_t addr) {
    asm volatile("ldmatrix.sync.aligned.m8n8.x4.shared.b16 {%0,%1,%2,%3}, [%4];"
        : "=r"(r[0]), "=r"(r[1]), "=r"(r[2]), "=r"(r[3]) : "r"(addr));
}
__device__ __forceinline__ void ldsm4t(uint32_t* r, uint32_t addr) {
    asm volatile("ldmatrix.sync.aligned.m8n8.x4.trans.shared.b16 {%0,%1,%2,%3}, [%4];"
        : "=r"(r[0]), "=r"(r[1]), "=r"(r[2]), "=r"(r[3]) : "r"(addr));
}
// bf16 MMA (attention)
__device__ __forceinline__ void hmma(float* c, const uint32_t* a, const uint32_t* b) {
    asm volatile("mma.sync.aligned.m16n8k16.row.col.f32.bf16.bf16.f32 "
        "{%0,%1,%2,%3}, {%4,%5,%6,%7}, {%8,%9}, {%0,%1,%2,%3};"
        : "+f"(c[0]), "+f"(c[1]), "+f"(c[2]), "+f"(c[3])
        : "r"(a[0]), "r"(a[1]), "r"(a[2]), "r"(a[3]), "r"(b[0]), "r"(b[1]));
}
// fp16 MMA (GEMMs)
__device__ __forceinline__ void hmma16(float* c, const uint32_t* a, const uint32_t* b) {
    asm volatile("mma.sync.aligned.m16n8k16.row.col.f32.f16.f16.f32 "
        "{%0,%1,%2,%3}, {%4,%5,%6,%7}, {%8,%9}, {%0,%1,%2,%3};"
        : "+f"(c[0]), "+f"(c[1]), "+f"(c[2]), "+f"(c[3])
        : "r"(a[0]), "r"(a[1]), "r"(a[2]), "r"(a[3]), "r"(b[0]), "r"(b[1]));
}
__device__ __forceinline__ void cpa16(uint32_t dst, const void* src) {
    asm volatile("cp.async.cg.shared.global [%0], [%1], 16;" :: "r"(dst), "l"(src));
}
#define CP_COMMIT() asm volatile("cp.async.commit_group;" ::: "memory")
#define CP_WAIT0()  asm volatile("cp.async.wait_group 0;" ::: "memory")
#define CP_WAIT1()  asm volatile("cp.async.wait_group 1;" ::: "memory")
#define CP_WAIT2()  asm volatile("cp.async.wait_group 2;" ::: "memory")

__device__ __forceinline__ uint32_t pack_bf16(__nv_bfloat16 a, __nv_bfloat16 b) {
    __nv_bfloat162 v = __halves2bfloat162(a, b);
    return *(uint32_t*)&v;
}
__device__ __forceinline__ void split_pair(float a, float b, uint32_t& hi, uint32_t& lo) {
    __nv_bfloat16 h0 = __float2bfloat16(a), h1 = __float2bfloat16(b);
    __nv_bfloat16 l0 = __float2bfloat16(a - __bfloat162float(h0));
    __nv_bfloat16 l1 = __float2bfloat16(b - __bfloat162float(h1));
    hi = pack_bf16(h0, h1); lo = pack_bf16(l0, l1);
}

// ---------------------------------------------------------------------------
// fp32 -> fp16, 4 elems/thread.
// ---------------------------------------------------------------------------
__global__ void cvt_f16(const float4* __restrict__ in, uint2* __restrict__ out, int n4)
{
    int i = blockIdx.x * blockDim.x + threadIdx.x;
    if (i >= n4) return;
    float4 v = in[i];
    __half2 a = __floats2half2_rn(v.x, v.y);
    __half2 b = __floats2half2_rn(v.z, v.w);
    uint2 o; o.x = *(uint32_t*)&a; o.y = *(uint32_t*)&b;
    out[i] = o;
}

// ---------------------------------------------------------------------------
// fp32 [K,N] -> transposed fp16 [N,K]
// ---------------------------------------------------------------------------
__global__ void cvt_f16_t(const float* __restrict__ in, __half* __restrict__ out,
                          int K, int N)
{
    __shared__ float t[32][33];
    const int n0 = blockIdx.x * 32, k0 = blockIdx.y * 32;
    const int tx = threadIdx.x, ty = threadIdx.y;
    #pragma unroll
    for (int j = ty; j < 32; j += 8)
        t[j][tx] = in[(size_t)(k0 + j) * N + n0 + tx];
    __syncthreads();
    #pragma unroll
    for (int j = ty; j < 32; j += 8)
        out[(size_t)(n0 + j) * K + k0 + tx] = __float2half(t[tx][j]);
}

// ---------------------------------------------------------------------------
// RoPE + scale + bf16 hi/lo split.  x fp32 [rows, nh, 128] -> xh/xl same layout.
// ---------------------------------------------------------------------------
__global__ void rope_split(const float* __restrict__ x, __nv_bfloat16* __restrict__ xh,
                           __nv_bfloat16* __restrict__ xl, int nh, int total, float scale)
{
    int idx = blockIdx.x * blockDim.x + threadIdx.x;
    if (idx >= total) return;
    int d = idx & 63;
    int t = idx >> 6;
    int row = t / nh;
    int pos = row & (Sn - 1);

    float freq = __expf(-(2.0f * (float)d / 128.0f) * 9.210340371976184f);
    float ang = (float)pos * freq;
    float sv = sinf(ang), cv = cosf(ang);

    const float* p = x + (size_t)t * 128 + 2 * d;
    float xe = p[0], xo = p[1];
    float r0 = (xe * cv - xo * sv) * scale;
    float r1 = (xe * sv + xo * cv) * scale;
    uint32_t hi, lo;
    split_pair(r0, r1, hi, lo);
    ((uint32_t*)xh)[(size_t)t * 64 + d] = hi;
    ((uint32_t*)xl)[(size_t)t * 64 + d] = lo;
}

// ---------------------------------------------------------------------------
// fp32 -> bf16 hi/lo split (for V), 4 elems/thread.
// ---------------------------------------------------------------------------
__global__ void cvt_hl(const float4* __restrict__ in, uint2* __restrict__ hi,
                       uint2* __restrict__ lo, int n4)
{
    int i = blockIdx.x * blockDim.x + threadIdx.x;
    if (i >= n4) return;
    float4 v = in[i];
    uint2 ho, lv;
    split_pair(v.x, v.y, ho.x, lv.x);
    split_pair(v.z, v.w, ho.y, lv.y);
    hi[i] = ho; lo[i] = lv;
}

// ---------------------------------------------------------------------------
// fp16 HMMA GEMM:  C[M,N] = A[M,K] @ B[N,K]^T + bias   (single-term fp16)
//   BM=128, BN=128, BK=64; 256 threads (8 warps, 4x2); 3-stage cp.async.
// Stage layout: A 16KB | B 16KB  (32KB per stage, 3 stages = 96KB)
// ---------------------------------------------------------------------------
#define STG 32768
#define GEMM_SMEM (3*STG)

__global__ __launch_bounds__(256)
void gemm_f16(const __half* __restrict__ A, const __half* __restrict__ B,
              const float* __restrict__ bias, float* __restrict__ C,
              int M, int N, int K)
{
    extern __shared__ char smem[];
    const uint32_t sb = smem_to_u32(smem);
    const int tid = threadIdx.x;
    const int wid = tid >> 5;
    const int lane = tid & 31;
    const int wm = wid >> 1;
    const int wn = wid & 1;
    const int row0 = blockIdx.y * 128;
    const int col0 = blockIdx.x * 128;

    const int ld_row = tid >> 3;
    const int ld_seg = tid & 7;

    float acc[2][8][4];
    #pragma unroll
    for (int a = 0; a < 2; ++a)
        #pragma unroll
        for (int b = 0; b < 8; ++b)
            #pragma unroll
            for (int c = 0; c < 4; ++c) acc[a][b][c] = 0.f;

    const int iters = K >> 6;

    auto issue = [&](int it, int stage) {
        const size_t kk = (size_t)(it << 6) + (ld_seg << 3);
        const uint32_t s0 = sb + stage * STG;
        #pragma unroll
        for (int j = 0; j < 4; ++j) {
            const int row = ld_row + j * 32;
            uint32_t bo = (uint32_t)(row * 128 + ld_seg * 16);
            uint32_t sw = bo ^ ((bo >> 3) & 0x70);
            cpa16(s0 + sw,         A + (size_t)(row0 + row) * K + kk);
            cpa16(s0 + 16384 + sw, B + (size_t)(col0 + row) * K + kk);
        }
        CP_COMMIT();
    };

    issue(0, 0);
    if (iters > 1) issue(1, 1);

    const int sub = lane >> 3;
    const int rr  = lane & 7;
    const int arow[2] = { wm*32 + 0*16 + (sub & 1)*8 + rr,
                          wm*32 + 1*16 + (sub & 1)*8 + rr };
    const int acol = (sub >> 1) * 16;
    const int brow[4] = { wn*64 + 0*16 + (sub >> 1)*8 + rr,
                          wn*64 + 1*16 + (sub >> 1)*8 + rr,
                          wn*64 + 2*16 + (sub >> 1)*8 + rr,
                          wn*64 + 3*16 + (sub >> 1)*8 + rr };
    const int bcol = (sub & 1) * 16;

    int stage = 0;
    for (int it = 0; it < iters; ++it) {
        if (it + 2 < iters) {
            int s2 = stage + 2; if (s2 >= 3) s2 -= 3;
            issue(it + 2, s2);
            CP_WAIT2();
        } else if (it + 1 < iters) {
            CP_WAIT1();
        } else {
            CP_WAIT0();
        }
        __syncthreads();

        const uint32_t sA = sb + stage * STG;
        const uint32_t sB = sA + 16384;

        #pragma unroll
        for (int ks = 0; ks < 4; ++ks) {
            uint32_t af[2][4], bf[4][4];
            #pragma unroll
            for (int mi = 0; mi < 2; ++mi) {
                uint32_t off = (uint32_t)(arow[mi] * 128 +
                               ((ks*32 + acol) ^ ((arow[mi] & 7) << 4)));
                ldsm4(af[mi], sA + off);
            }
            #pragma unroll
            for (int p = 0; p < 4; ++p) {
                uint32_t off = (uint32_t)(brow[p] * 128 +
                               ((ks*32 + bcol) ^ ((brow[p] & 7) << 4)));
                ldsm4(bf[p], sB + off);
            }
            #pragma unroll
            for (int mi = 0; mi < 2; ++mi)
                #pragma unroll
                for (int ni = 0; ni < 8; ++ni)
                    hmma16(acc[mi][ni], af[mi], &bf[ni >> 1][(ni & 1) * 2]);
        }
        __syncthreads();
        if (++stage == 3) stage = 0;
    }

    const int g = lane >> 2, t = lane & 3;
    #pragma unroll
    for (int mi = 0; mi < 2; ++mi) {
        const int rlo = row0 + wm*32 + mi*16 + g;
        #pragma unroll
        for (int ni = 0; ni < 8; ++ni) {
            const int col = col0 + wn*64 + ni*8 + 2*t;
            const float b0 = bias[col], b1 = bias[col + 1];
            float2 lo = make_float2(acc[mi][ni][0] + b0, acc[mi][ni][1] + b1);
            float2 hi = make_float2(acc[mi][ni][2] + b0, acc[mi][ni][3] + b1);
            *(float2*)(C + (size_t)rlo * N + col)       = lo;
            *(float2*)(C + (size_t)(rlo + 8) * N + col) = hi;
        }
    }
}

// ---------------------------------------------------------------------------
// Flash attention on HMMA, split-bf16 for QK^T and P*V. (as R4, fp16 output)
// SMEM map (bytes):
//   Qh 0, Ql 17408; KV buf{0,1} at 34816 + buf*69632: Kh,Kl,Vh,Vl (17408 ea)
//   Ph 174080, Pl 183296;  total 192512
// ---------------------------------------------------------------------------
#define ATT_SMEM 192512

__global__ __launch_bounds__(128, 1)
void attn_mma(const __nv_bfloat16* __restrict__ qh, const __nv_bfloat16* __restrict__ ql,
              const __nv_bfloat16* __restrict__ kh, const __nv_bfloat16* __restrict__ kl,
              const __nv_bfloat16* __restrict__ vh, const __nv_bfloat16* __restrict__ vl,
              __half* __restrict__ of)
{
    extern __shared__ char smem[];
    const uint32_t sb = smem_to_u32(smem);
    const int tid = threadIdx.x, lane = tid & 31, wq = tid >> 5;
    const int i0 = blockIdx.x * 64;
    const int h  = blockIdx.y, b = blockIdx.z, kvh = h >> 2;

    for (int c = tid; c < 1024; c += 128) {
        int r = c >> 4, ch = c & 15;
        uint32_t dst = sb + r * 272 + ch * 16;
        size_t src = (((size_t)(b * Sn + i0 + r) * NQ + h) * 128) + ch * 8;
        cpa16(dst,         qh + src);
        cpa16(dst + 17408, ql + src);
    }
    CP_COMMIT();

    int jt0 = i0 - WINDOW; if (jt0 < 0) jt0 = 0;
    const int ntiles = (i0 - jt0) / 64 + 1;

    auto stage_kv = [&](int t, int buf) {
        int jt = jt0 + t * 64;
        uint32_t s0 = sb + 34816 + buf * 69632;
        for (int c = tid; c < 1024; c += 128) {
            int r = c >> 4, ch = c & 15;
            uint32_t dst = s0 + r * 272 + ch * 16;
            size_t src = (((size_t)(b * Sn + jt + r) * NKV + kvh) * 128) + ch * 8;
            cpa16(dst,         kh + src);
            cpa16(dst + 17408, kl + src);
            cpa16(dst + 34816, vh + src);
            cpa16(dst + 52224, vl + src);
        }
        CP_COMMIT();
    };

    stage_kv(0, 0);

    const int g = lane >> 2, t4 = lane & 3;
    const int a_r  = ((lane >> 3) & 1) * 8 + (lane & 7);
    const int a_c8 = (lane >> 4) & 1;

    float m_r[2] = {-1e30f, -1e30f};
    float l_r[2] = {0.f, 0.f};
    float o_acc[16][4];
    #pragma unroll
    for (int nb = 0; nb < 16; ++nb)
        #pragma unroll
        for (int c = 0; c < 4; ++c) o_acc[nb][c] = 0.f;

    const uint32_t sPh = sb + 174080, sPl = sb + 183296;

    for (int t = 0; t < ntiles; ++t) {
        const int buf = t & 1;
        if (t + 1 < ntiles) { stage_kv(t + 1, buf ^ 1); CP_WAIT1(); }
        else                { CP_WAIT0(); }
        __syncthreads();

        const uint32_t sQh = sb, sQl = sb + 17408;
        const uint32_t sKh = sb + 34816 + buf * 69632;
        const uint32_t sKl = sKh + 17408;
        const uint32_t sVh = sKh + 34816;
        const uint32_t sVl = sKh + 52224;

        float s_c[8][4];
        #pragma unroll
        for (int nb = 0; nb < 8; ++nb)
            #pragma unroll
            for (int c = 0; c < 4; ++c) s_c[nb][c] = 0.f;

        #pragma unroll
        for (int ks = 0; ks < 8; ++ks) {
            uint32_t ah[4], al[4];
            uint32_t qoff = (uint32_t)((wq * 16 + a_r) * 272 + (ks * 16 + a_c8 * 8) * 2);
            ldsm4(ah, sQh + qoff);
            ldsm4(al, sQl + qoff);
            #pragma unroll
            for (int p = 0; p < 4; ++p) {
                uint32_t bh[4], bl[4];
                uint32_t koff = (uint32_t)((p * 16 + a_r) * 272 + (ks * 16 + a_c8 * 8) * 2);
                ldsm4(bh, sKh + koff);
                ldsm4(bl, sKl + koff);
                uint32_t bh0[2] = {bh[0], bh[2]}, bh1[2] = {bh[1], bh[3]};
                uint32_t bl0[2] = {bl[0], bl[2]}, bl1[2] = {bl[1], bl[3]};
                hmma(s_c[2*p],   ah, bh0);
                hmma(s_c[2*p+1], ah, bh1);
                hmma(s_c[2*p],   ah, bl0);
                hmma(s_c[2*p+1], ah, bl1);
                hmma(s_c[2*p],   al, bh0);
                hmma(s_c[2*p+1], al, bh1);
            }
        }

        const int jt = jt0 + t * 64;
        float mt[2] = {-1e30f, -1e30f};
        #pragma unroll
        for (int nb = 0; nb < 8; ++nb) {
            const int jbase = jt + nb * 8 + t4 * 2;
            #pragma unroll
            for (int c = 0; c < 4; ++c) {
                const int rr = c >> 1;
                const int i = i0 + wq * 16 + g + rr * 8;
                const int j = jbase + (c & 1);
                if (!((j <= i) && (i - j <= WINDOW)))
                    s_c[nb][c] = -1e30f;
                mt[rr] = fmaxf(mt[rr], s_c[nb][c]);
            }
        }
        float corr[2];
        #pragma unroll
        for (int rr = 0; rr < 2; ++rr) {
            mt[rr] = fmaxf(mt[rr], __shfl_xor_sync(0xffffffffu, mt[rr], 1));
            mt[rr] = fmaxf(mt[rr], __shfl_xor_sync(0xffffffffu, mt[rr], 2));
            float mn = fmaxf(m_r[rr], mt[rr]);
            corr[rr] = __expf(m_r[rr] - mn);
            m_r[rr] = mn;
        }
        float ps[2] = {0.f, 0.f};
        #pragma unroll
        for (int nb = 0; nb < 8; ++nb) {
            #pragma unroll
            for (int c = 0; c < 4; ++c) {
                const int rr = c >> 1;
                float p = __expf(s_c[nb][c] - m_r[rr]);
                s_c[nb][c] = p;
                ps[rr] += p;
            }
        }
        #pragma unroll
        for (int rr = 0; rr < 2; ++rr) {
            ps[rr] += __shfl_xor_sync(0xffffffffu, ps[rr], 1);
            ps[rr] += __shfl_xor_sync(0xffffffffu, ps[rr], 2);
            l_r[rr] = l_r[rr] * corr[rr] + ps[rr];
        }
        #pragma unroll
        for (int nb = 0; nb < 16; ++nb) {
            o_acc[nb][0] *= corr[0]; o_acc[nb][1] *= corr[0];
            o_acc[nb][2] *= corr[1]; o_acc[nb][3] *= corr[1];
        }

        #pragma unroll
        for (int nb = 0; nb < 8; ++nb) {
            #pragma unroll
            for (int rr = 0; rr < 2; ++rr) {
                uint32_t hi, lo;
                split_pair(s_c[nb][rr*2], s_c[nb][rr*2+1], hi, lo);
                const int row = wq * 16 + g + rr * 8;
                uint32_t off = (uint32_t)(row * 144 + (nb * 8 + t4 * 2) * 2);
                asm volatile("st.shared.b32 [%0], %1;" :: "r"(sPh + off), "r"(hi) : "memory");
                asm volatile("st.shared.b32 [%0], %1;" :: "r"(sPl + off), "r"(lo) : "memory");
            }
        }
        __syncwarp();

        #pragma unroll
        for (int ks = 0; ks < 4; ++ks) {
            uint32_t aph[4], apl[4];
            uint32_t poff = (uint32_t)((wq * 16 + a_r) * 144 + (ks * 16 + a_c8 * 8) * 2);
            ldsm4(aph, sPh + poff);
            ldsm4(apl, sPl + poff);
            #pragma unroll
            for (int p2 = 0; p2 < 8; ++p2) {
                uint32_t bvh[4], bvl[4];
                uint32_t voff = (uint32_t)((ks * 16 + a_r) * 272 + (p2 * 16 + a_c8 * 8) * 2);
                ldsm4t(bvh, sVh + voff);
                ldsm4t(bvl, sVl + voff);
                uint32_t bh0[2] = {bvh[0], bvh[1]}, bh1[2] = {bvh[2], bvh[3]};
                uint32_t bl0[2] = {bvl[0], bvl[1]}, bl1[2] = {bvl[2], bvl[3]};
                hmma(o_acc[2*p2],   aph, bh0);
                hmma(o_acc[2*p2+1], aph, bh1);
                hmma(o_acc[2*p2],   apl, bh0);
                hmma(o_acc[2*p2+1], apl, bh1);
                hmma(o_acc[2*p2],   aph, bl0);
                hmma(o_acc[2*p2+1], aph, bl1);
            }
        }
        __syncthreads();
    }

    // epilogue: normalize, write fp16
    const float inv0 = 1.0f / l_r[0], inv1 = 1.0f / l_r[1];
    #pragma unroll
    for (int nb = 0; nb < 16; ++nb) {
        const int d = nb * 8 + t4 * 2;
        #pragma unroll
        for (int rr = 0; rr < 2; ++rr) {
            const int i = i0 + wq * 16 + g + rr * 8;
            const float inv = rr ? inv1 : inv0;
            __half2 hv = __floats2half2_rn(o_acc[nb][rr*2] * inv, o_acc[nb][rr*2+1] * inv);
            const size_t o32 = ((size_t)(b * Sn + i) * NQ + h) * 64 + (d >> 1);
            ((uint32_t*)of)[o32] = *(uint32_t*)&hv;
        }
    }
}

// ---------------------------------------------------------------------------
extern "C" void kernel_launch(void* const* d_in, const int* in_sizes, int n_in,
                              void* d_out, int out_size)
{
    const float* x  = (const float*)d_in[0];
    const float* Wq = (const float*)d_in[1];
    const float* bq = (const float*)d_in[2];
    const float* Wk = (const float*)d_in[3];
    const float* bk = (const float*)d_in[4];
    const float* Wv = (const float*)d_in[5];
    const float* bv = (const float*)d_in[6];
    const float* Wo = (const float*)d_in[7];
    const float* bo = (const float*)d_in[8];
    float* out = (float*)d_out;

    float *qp, *kp, *vp;
    cudaGetSymbolAddress((void**)&qp, g_q);
    cudaGetSymbolAddress((void**)&kp, g_k);
    cudaGetSymbolAddress((void**)&vp, g_v);
    __half *xf, *of, *wq, *wk, *wv, *wo;
    cudaGetSymbolAddress((void**)&xf, g_xf); cudaGetSymbolAddress((void**)&of, g_of);
    cudaGetSymbolAddress((void**)&wq, g_wq); cudaGetSymbolAddress((void**)&wk, g_wk);
    cudaGetSymbolAddress((void**)&wv, g_wv); cudaGetSymbolAddress((void**)&wo, g_wo);
    __nv_bfloat16 *qhb, *qlb, *khb, *klb, *vhb, *vlb;
    cudaGetSymbolAddress((void**)&qhb, g_qhb); cudaGetSymbolAddress((void**)&qlb, g_qlb);
    cudaGetSymbolAddress((void**)&khb, g_khb); cudaGetSymbolAddress((void**)&klb, g_klb);
    cudaGetSymbolAddress((void**)&vhb, g_vhb); cudaGetSymbolAddress((void**)&vlb, g_vlb);

    cudaFuncSetAttribute(gemm_f16, cudaFuncAttributeMaxDynamicSharedMemorySize, GEMM_SMEM);
    cudaFuncSetAttribute(attn_mma, cudaFuncAttributeMaxDynamicSharedMemorySize, ATT_SMEM);

    // Converts
    const int n4x = Mrows * En / 4;
    cvt_f16<<<n4x / 1024, 1024>>>((const float4*)x, (uint2*)xf, n4x);
    dim3 tb(32, 8);
    cvt_f16_t<<<dim3(64, 64), tb>>>(Wq, wq, 2048, 2048);
    cvt_f16_t<<<dim3(16, 64), tb>>>(Wk, wk, 2048, 512);
    cvt_f16_t<<<dim3(16, 64), tb>>>(Wv, wv, 2048, 512);
    cvt_f16_t<<<dim3(64, 64), tb>>>(Wo, wo, 2048, 2048);

    // QKV projections (fp16 HMMA)
    gemm_f16<<<dim3(2048/128, Mrows/128), 256, GEMM_SMEM>>>(xf, wq, bq, qp, Mrows, 2048, En);
    gemm_f16<<<dim3(512/128,  Mrows/128), 256, GEMM_SMEM>>>(xf, wk, bk, kp, Mrows, 512, En);
    gemm_f16<<<dim3(512/128,  Mrows/128), 256, GEMM_SMEM>>>(xf, wv, bv, vp, Mrows, 512, En);

    // RoPE + split (q scaled by 1/sqrt(HD)), v split (bf16 hi/lo)
    {
        int totq = Mrows * NQ * 64;
        rope_split<<<(totq + 255) / 256, 256>>>(qp, qhb, qlb, NQ, totq, 0.08838834764831845f);
        int totk = Mrows * NKV * 64;
        rope_split<<<(totk + 255) / 256, 256>>>(kp, khb, klb, NKV, totk, 1.0f);
        int n4v = Mrows * NKV * HD / 4;
        cvt_hl<<<(n4v + 1023) / 1024, 1024>>>((const float4*)vp, (uint2*)vhb, (uint2*)vlb, n4v);
    }

    // Flash attention (bf16 split HMMA), fp16 output
    attn_mma<<<dim3(Sn/64, NQ, Bn), 128, ATT_SMEM>>>(qhb, qlb, khb, klb, vhb, vlb, of);

    // Output projection (fp16 HMMA)
    gemm_f16<<<dim3(2048/128, Mrows/128), 256, GEMM_SMEM>>>(of, wo, bo, out, Mrows, 2048, En);
}

// round 6
// speedup vs baseline: 9.9840x; 1.2512x over previous
#include <cuda_runtime.h>
#include <cuda_bf16.h>
#include <cuda_fp16.h>
#include <math.h>
#include <cstdint>

// Problem constants
#define Bn 2
#define Sn 2048
#define En 2048
#define NQ 16
#define NKV 4
#define HD 128
#define WINDOW 512
#define Mrows (Bn*Sn)          // 4096

// ---------------------------------------------------------------------------
// Scratch (device globals; no allocation allowed)
// ---------------------------------------------------------------------------
__device__ float g_q[(size_t)Mrows * NQ * HD];     // fp32 q (pre-rope)
__device__ float g_k[(size_t)Mrows * NKV * HD];
__device__ float g_v[(size_t)Mrows * NKV * HD];

// fp16 activations / weights (GEMMs)
__device__ __half g_xf[(size_t)Mrows * En];
__device__ __half g_of[(size_t)Mrows * En];        // attention out, fp16
__device__ __half g_wq[(size_t)2048 * 2048];       // [N,K]
__device__ __half g_wk[(size_t)512 * 2048];
__device__ __half g_wv[(size_t)512 * 2048];
__device__ __half g_wo[(size_t)2048 * 2048];

// attention operands: q fp16 hi/lo (2-term), k/v single fp16
__device__ __half g_qh16[(size_t)Mrows * NQ * HD];
__device__ __half g_ql16[(size_t)Mrows * NQ * HD];
__device__ __half g_kf16[(size_t)Mrows * NKV * HD];
__device__ __half g_vf16[(size_t)Mrows * NKV * HD];

// ---------------------------------------------------------------------------
// PTX helpers (base sm_103: mma.sync / ldmatrix / cp.async)
// ---------------------------------------------------------------------------
__device__ __forceinline__ uint32_t smem_to_u32(const void* p) {
    uint32_t a;
    asm("{ .reg .u64 t; cvta.to.shared.u64 t, %1; cvt.u32.u64 %0, t; }" : "=r"(a) : "l"(p));
    return a;
}
__device__ __forceinline__ void ldsm4(uint32_t* r, uint32_t addr) {
    asm volatile("ldmatrix.sync.aligned.m8n8.x4.shared.b16 {%0,%1,%2,%3}, [%4];"
        : "=r"(r[0]), "=r"(r[1]), "=r"(r[2]), "=r"(r[3]) : "r"(addr));
}
__device__ __forceinline__ void ldsm4t(uint32_t* r, uint32_t addr) {
    asm volatile("ldmatrix.sync.aligned.m8n8.x4.trans.shared.b16 {%0,%1,%2,%3}, [%4];"
        : "=r"(r[0]), "=r"(r[1]), "=r"(r[2]), "=r"(r[3]) : "r"(addr));
}
// fp16 MMA
__device__ __forceinline__ void hmma16(float* c, const uint32_t* a, const uint32_t* b) {
    asm volatile("mma.sync.aligned.m16n8k16.row.col.f32.f16.f16.f32 "
        "{%0,%1,%2,%3}, {%4,%5,%6,%7}, {%8,%9}, {%0,%1,%2,%3};"
        : "+f"(c[0]), "+f"(c[1]), "+f"(c[2]), "+f"(c[3])
        : "r"(a[0]), "r"(a[1]), "r"(a[2]), "r"(a[3]), "r"(b[0]), "r"(b[1]));
}
__device__ __forceinline__ void cpa16(uint32_t dst, const void* src) {
    asm volatile("cp.async.cg.shared.global [%0], [%1], 16;" :: "r"(dst), "l"(src));
}
#define CP_COMMIT() asm volatile("cp.async.commit_group;" ::: "memory")
#define CP_WAIT0()  asm volatile("cp.async.wait_group 0;" ::: "memory")
#define CP_WAIT1()  asm volatile("cp.async.wait_group 1;" ::: "memory")
#define CP_WAIT2()  asm volatile("cp.async.wait_group 2;" ::: "memory")

// fp16 hi/lo split of a float pair, packed as u32s
__device__ __forceinline__ void split_pair_h(float a, float b, uint32_t& hi, uint32_t& lo) {
    __half h0 = __float2half_rn(a), h1 = __float2half_rn(b);
    __half l0 = __float2half_rn(a - __half2float(h0));
    __half l1 = __float2half_rn(b - __half2float(h1));
    __half2 H = __halves2half2(h0, h1), L = __halves2half2(l0, l1);
    hi = *(uint32_t*)&H; lo = *(uint32_t*)&L;
}

// ---------------------------------------------------------------------------
// fp32 -> fp16, 4 elems/thread.
// ---------------------------------------------------------------------------
__global__ void cvt_f16(const float4* __restrict__ in, uint2* __restrict__ out, int n4)
{
    int i = blockIdx.x * blockDim.x + threadIdx.x;
    if (i >= n4) return;
    float4 v = in[i];
    __half2 a = __floats2half2_rn(v.x, v.y);
    __half2 b = __floats2half2_rn(v.z, v.w);
    uint2 o; o.x = *(uint32_t*)&a; o.y = *(uint32_t*)&b;
    out[i] = o;
}

// ---------------------------------------------------------------------------
// fp32 [K,N] -> transposed fp16 [N,K]
// ---------------------------------------------------------------------------
__global__ void cvt_f16_t(const float* __restrict__ in, __half* __restrict__ out,
                          int K, int N)
{
    __shared__ float t[32][33];
    const int n0 = blockIdx.x * 32, k0 = blockIdx.y * 32;
    const int tx = threadIdx.x, ty = threadIdx.y;
    #pragma unroll
    for (int j = ty; j < 32; j += 8)
        t[j][tx] = in[(size_t)(k0 + j) * N + n0 + tx];
    __syncthreads();
    #pragma unroll
    for (int j = ty; j < 32; j += 8)
        out[(size_t)(n0 + j) * K + k0 + tx] = __float2half(t[tx][j]);
}

// ---------------------------------------------------------------------------
// RoPE + scale + fp16 hi/lo split (Q).  x fp32 [rows, nh, 128] -> xh/xl.
// ---------------------------------------------------------------------------
__global__ void rope_split_q(const float* __restrict__ x, __half* __restrict__ xh,
                             __half* __restrict__ xl, int nh, int total, float scale)
{
    int idx = blockIdx.x * blockDim.x + threadIdx.x;
    if (idx >= total) return;
    int d = idx & 63;
    int t = idx >> 6;
    int row = t / nh;
    int pos = row & (Sn - 1);

    float freq = __expf(-(2.0f * (float)d / 128.0f) * 9.210340371976184f);
    float ang = (float)pos * freq;
    float sv = sinf(ang), cv = cosf(ang);

    const float* p = x + (size_t)t * 128 + 2 * d;
    float xe = p[0], xo = p[1];
    float r0 = (xe * cv - xo * sv) * scale;
    float r1 = (xe * sv + xo * cv) * scale;
    uint32_t hi, lo;
    split_pair_h(r0, r1, hi, lo);
    ((uint32_t*)xh)[(size_t)t * 64 + d] = hi;
    ((uint32_t*)xl)[(size_t)t * 64 + d] = lo;
}

// ---------------------------------------------------------------------------
// RoPE + single fp16 (K).
// ---------------------------------------------------------------------------
__global__ void rope_one(const float* __restrict__ x, __half* __restrict__ xf,
                         int nh, int total)
{
    int idx = blockIdx.x * blockDim.x + threadIdx.x;
    if (idx >= total) return;
    int d = idx & 63;
    int t = idx >> 6;
    int row = t / nh;
    int pos = row & (Sn - 1);

    float freq = __expf(-(2.0f * (float)d / 128.0f) * 9.210340371976184f);
    float ang = (float)pos * freq;
    float sv = sinf(ang), cv = cosf(ang);

    const float* p = x + (size_t)t * 128 + 2 * d;
    float xe = p[0], xo = p[1];
    __half2 hv = __floats2half2_rn(xe * cv - xo * sv, xe * sv + xo * cv);
    ((uint32_t*)xf)[(size_t)t * 64 + d] = *(uint32_t*)&hv;
}

// ---------------------------------------------------------------------------
// fp16 HMMA GEMM (unchanged from R5):  C = A[M,K] @ B[N,K]^T + bias
// ---------------------------------------------------------------------------
#define STG 32768
#define GEMM_SMEM (3*STG)

__global__ __launch_bounds__(256)
void gemm_f16(const __half* __restrict__ A, const __half* __restrict__ B,
              const float* __restrict__ bias, float* __restrict__ C,
              int M, int N, int K)
{
    extern __shared__ char smem[];
    const uint32_t sb = smem_to_u32(smem);
    const int tid = threadIdx.x;
    const int wid = tid >> 5;
    const int lane = tid & 31;
    const int wm = wid >> 1;
    const int wn = wid & 1;
    const int row0 = blockIdx.y * 128;
    const int col0 = blockIdx.x * 128;

    const int ld_row = tid >> 3;
    const int ld_seg = tid & 7;

    float acc[2][8][4];
    #pragma unroll
    for (int a = 0; a < 2; ++a)
        #pragma unroll
        for (int b = 0; b < 8; ++b)
            #pragma unroll
            for (int c = 0; c < 4; ++c) acc[a][b][c] = 0.f;

    const int iters = K >> 6;

    auto issue = [&](int it, int stage) {
        const size_t kk = (size_t)(it << 6) + (ld_seg << 3);
        const uint32_t s0 = sb + stage * STG;
        #pragma unroll
        for (int j = 0; j < 4; ++j) {
            const int row = ld_row + j * 32;
            uint32_t bo = (uint32_t)(row * 128 + ld_seg * 16);
            uint32_t sw = bo ^ ((bo >> 3) & 0x70);
            cpa16(s0 + sw,         A + (size_t)(row0 + row) * K + kk);
            cpa16(s0 + 16384 + sw, B + (size_t)(col0 + row) * K + kk);
        }
        CP_COMMIT();
    };

    issue(0, 0);
    if (iters > 1) issue(1, 1);

    const int sub = lane >> 3;
    const int rr  = lane & 7;
    const int arow[2] = { wm*32 + 0*16 + (sub & 1)*8 + rr,
                          wm*32 + 1*16 + (sub & 1)*8 + rr };
    const int acol = (sub >> 1) * 16;
    const int brow[4] = { wn*64 + 0*16 + (sub >> 1)*8 + rr,
                          wn*64 + 1*16 + (sub >> 1)*8 + rr,
                          wn*64 + 2*16 + (sub >> 1)*8 + rr,
                          wn*64 + 3*16 + (sub >> 1)*8 + rr };
    const int bcol = (sub & 1) * 16;

    int stage = 0;
    for (int it = 0; it < iters; ++it) {
        if (it + 2 < iters) {
            int s2 = stage + 2; if (s2 >= 3) s2 -= 3;
            issue(it + 2, s2);
            CP_WAIT2();
        } else if (it + 1 < iters) {
            CP_WAIT1();
        } else {
            CP_WAIT0();
        }
        __syncthreads();

        const uint32_t sA = sb + stage * STG;
        const uint32_t sB = sA + 16384;

        #pragma unroll
        for (int ks = 0; ks < 4; ++ks) {
            uint32_t af[2][4], bf[4][4];
            #pragma unroll
            for (int mi = 0; mi < 2; ++mi) {
                uint32_t off = (uint32_t)(arow[mi] * 128 +
                               ((ks*32 + acol) ^ ((arow[mi] & 7) << 4)));
                ldsm4(af[mi], sA + off);
            }
            #pragma unroll
            for (int p = 0; p < 4; ++p) {
                uint32_t off = (uint32_t)(brow[p] * 128 +
                               ((ks*32 + bcol) ^ ((brow[p] & 7) << 4)));
                ldsm4(bf[p], sB + off);
            }
            #pragma unroll
            for (int mi = 0; mi < 2; ++mi)
                #pragma unroll
                for (int ni = 0; ni < 8; ++ni)
                    hmma16(acc[mi][ni], af[mi], &bf[ni >> 1][(ni & 1) * 2]);
        }
        __syncthreads();
        if (++stage == 3) stage = 0;
    }

    const int g = lane >> 2, t = lane & 3;
    #pragma unroll
    for (int mi = 0; mi < 2; ++mi) {
        const int rlo = row0 + wm*32 + mi*16 + g;
        #pragma unroll
        for (int ni = 0; ni < 8; ++ni) {
            const int col = col0 + wn*64 + ni*8 + 2*t;
            const float b0 = bias[col], b1 = bias[col + 1];
            float2 lo = make_float2(acc[mi][ni][0] + b0, acc[mi][ni][1] + b1);
            float2 hi = make_float2(acc[mi][ni][2] + b0, acc[mi][ni][3] + b1);
            *(float2*)(C + (size_t)rlo * N + col)       = lo;
            *(float2*)(C + (size_t)(rlo + 8) * N + col) = hi;
        }
    }
}

// ---------------------------------------------------------------------------
// Flash attention, fp16 2-term:
//   S = (Qh + Ql) * K^T   (2 fp16 MMAs, K single fp16)
//   O = P * V             (1 fp16 MMA, P/V single fp16)
// Block: (q-tile 64, h, b). 4 warps x 16 q rows. j-tiles of 64.
// SMEM map (bytes):
//   Qh 0, Ql 17408                                 (64 rows x 272B)
//   KV buf{0,1} at 34816 + buf*34816: Kf, Vf       (each 17408)
//   Pf 104448                                      (64 rows x 144B)
// total 113664
// ---------------------------------------------------------------------------
#define ATT_SMEM 113664

__global__ __launch_bounds__(128)
void attn_mma(const __half* __restrict__ qh, const __half* __restrict__ ql,
              const __half* __restrict__ kf, const __half* __restrict__ vf,
              __half* __restrict__ of)
{
    extern __shared__ char smem[];
    const uint32_t sb = smem_to_u32(smem);
    const int tid = threadIdx.x, lane = tid & 31, wq = tid >> 5;
    const int i0 = blockIdx.x * 64;
    const int h  = blockIdx.y, b = blockIdx.z, kvh = h >> 2;

    // stage Q (once)
    for (int c = tid; c < 1024; c += 128) {
        int r = c >> 4, ch = c & 15;
        uint32_t dst = sb + r * 272 + ch * 16;
        size_t src = (((size_t)(b * Sn + i0 + r) * NQ + h) * 128) + ch * 8;
        cpa16(dst,         qh + src);
        cpa16(dst + 17408, ql + src);
    }
    CP_COMMIT();

    int jt0 = i0 - WINDOW; if (jt0 < 0) jt0 = 0;
    const int ntiles = (i0 - jt0) / 64 + 1;
    const bool mask_first = (i0 - jt0) == WINDOW;

    auto stage_kv = [&](int t, int buf) {
        int jt = jt0 + t * 64;
        uint32_t s0 = sb + 34816 + buf * 34816;
        for (int c = tid; c < 1024; c += 128) {
            int r = c >> 4, ch = c & 15;
            uint32_t dst = s0 + r * 272 + ch * 16;
            size_t src = (((size_t)(b * Sn + jt + r) * NKV + kvh) * 128) + ch * 8;
            cpa16(dst,         kf + src);
            cpa16(dst + 17408, vf + src);
        }
        CP_COMMIT();
    };

    stage_kv(0, 0);

    const int g = lane >> 2, t4 = lane & 3;
    const int a_r  = ((lane >> 3) & 1) * 8 + (lane & 7);
    const int a_c8 = (lane >> 4) & 1;

    float m_r[2] = {-1e30f, -1e30f};
    float l_r[2] = {0.f, 0.f};
    float o_acc[16][4];
    #pragma unroll
    for (int nb = 0; nb < 16; ++nb)
        #pragma unroll
        for (int c = 0; c < 4; ++c) o_acc[nb][c] = 0.f;

    const uint32_t sPf = sb + 104448;

    for (int t = 0; t < ntiles; ++t) {
        const int buf = t & 1;
        if (t + 1 < ntiles) { stage_kv(t + 1, buf ^ 1); CP_WAIT1(); }
        else                { CP_WAIT0(); }
        __syncthreads();

        const uint32_t sQh = sb, sQl = sb + 17408;
        const uint32_t sKf = sb + 34816 + buf * 34816;
        const uint32_t sVf = sKf + 17408;

        // ---- S = (Qh + Ql) K^T ----
        float s_c[8][4];
        #pragma unroll
        for (int nb = 0; nb < 8; ++nb)
            #pragma unroll
            for (int c = 0; c < 4; ++c) s_c[nb][c] = 0.f;

        #pragma unroll
        for (int ks = 0; ks < 8; ++ks) {
            uint32_t ah[4], al[4];
            uint32_t qoff = (uint32_t)((wq * 16 + a_r) * 272 + (ks * 16 + a_c8 * 8) * 2);
            ldsm4(ah, sQh + qoff);
            ldsm4(al, sQl + qoff);
            #pragma unroll
            for (int p = 0; p < 4; ++p) {
                uint32_t bf[4];
                uint32_t koff = (uint32_t)((p * 16 + a_r) * 272 + (ks * 16 + a_c8 * 8) * 2);
                ldsm4(bf, sKf + koff);
                uint32_t b0[2] = {bf[0], bf[2]}, b1[2] = {bf[1], bf[3]};
                hmma16(s_c[2*p],   ah, b0);
                hmma16(s_c[2*p+1], ah, b1);
                hmma16(s_c[2*p],   al, b0);
                hmma16(s_c[2*p+1], al, b1);
            }
        }

        // ---- mask (only first/last tile) + online softmax ----
        const int jt = jt0 + t * 64;
        const bool need_mask = (t == ntiles - 1) || (t == 0 && mask_first);
        float mt[2] = {-1e30f, -1e30f};
        if (need_mask) {
            #pragma unroll
            for (int nb = 0; nb < 8; ++nb) {
                const int jbase = jt + nb * 8 + t4 * 2;
                #pragma unroll
                for (int c = 0; c < 4; ++c) {
                    const int rr = c >> 1;
                    const int i = i0 + wq * 16 + g + rr * 8;
                    const int j = jbase + (c & 1);
                    if (!((j <= i) && (i - j <= WINDOW)))
                        s_c[nb][c] = -1e30f;
                    mt[rr] = fmaxf(mt[rr], s_c[nb][c]);
                }
            }
        } else {
            #pragma unroll
            for (int nb = 0; nb < 8; ++nb)
                #pragma unroll
                for (int c = 0; c < 4; ++c)
                    mt[c >> 1] = fmaxf(mt[c >> 1], s_c[nb][c]);
        }
        float corr[2];
        #pragma unroll
        for (int rr = 0; rr < 2; ++rr) {
            mt[rr] = fmaxf(mt[rr], __shfl_xor_sync(0xffffffffu, mt[rr], 1));
            mt[rr] = fmaxf(mt[rr], __shfl_xor_sync(0xffffffffu, mt[rr], 2));
            float mn = fmaxf(m_r[rr], mt[rr]);
            corr[rr] = __expf(m_r[rr] - mn);
            m_r[rr] = mn;
        }
        float ps[2] = {0.f, 0.f};
        #pragma unroll
        for (int nb = 0; nb < 8; ++nb) {
            #pragma unroll
            for (int c = 0; c < 4; ++c) {
                const int rr = c >> 1;
                float p = __expf(s_c[nb][c] - m_r[rr]);
                s_c[nb][c] = p;
                ps[rr] += p;
            }
        }
        #pragma unroll
        for (int rr = 0; rr < 2; ++rr) {
            ps[rr] += __shfl_xor_sync(0xffffffffu, ps[rr], 1);
            ps[rr] += __shfl_xor_sync(0xffffffffu, ps[rr], 2);
            l_r[rr] = l_r[rr] * corr[rr] + ps[rr];
        }
        #pragma unroll
        for (int nb = 0; nb < 16; ++nb) {
            o_acc[nb][0] *= corr[0]; o_acc[nb][1] *= corr[0];
            o_acc[nb][2] *= corr[1]; o_acc[nb][3] *= corr[1];
        }

        // ---- P -> smem (single fp16) ----
        #pragma unroll
        for (int nb = 0; nb < 8; ++nb) {
            #pragma unroll
            for (int rr = 0; rr < 2; ++rr) {
                __half2 pv = __floats2half2_rn(s_c[nb][rr*2], s_c[nb][rr*2+1]);
                const int row = wq * 16 + g + rr * 8;
                uint32_t off = (uint32_t)(row * 144 + (nb * 8 + t4 * 2) * 2);
                asm volatile("st.shared.b32 [%0], %1;"
                    :: "r"(sPf + off), "r"(*(uint32_t*)&pv) : "memory");
            }
        }
        __syncwarp();

        // ---- O += P * V ----
        #pragma unroll
        for (int ks = 0; ks < 4; ++ks) {
            uint32_t apf[4];
            uint32_t poff = (uint32_t)((wq * 16 + a_r) * 144 + (ks * 16 + a_c8 * 8) * 2);
            ldsm4(apf, sPf + poff);
            #pragma unroll
            for (int p2 = 0; p2 < 8; ++p2) {
                uint32_t bvf[4];
                uint32_t voff = (uint32_t)((ks * 16 + a_r) * 272 + (p2 * 16 + a_c8 * 8) * 2);
                ldsm4t(bvf, sVf + voff);
                uint32_t b0[2] = {bvf[0], bvf[1]}, b1[2] = {bvf[2], bvf[3]};
                hmma16(o_acc[2*p2],   apf, b0);
                hmma16(o_acc[2*p2+1], apf, b1);
            }
        }
        __syncthreads();
    }

    // ---- epilogue: normalize, write fp16 ----
    const float inv0 = 1.0f / l_r[0], inv1 = 1.0f / l_r[1];
    #pragma unroll
    for (int nb = 0; nb < 16; ++nb) {
        const int d = nb * 8 + t4 * 2;
        #pragma unroll
        for (int rr = 0; rr < 2; ++rr) {
            const int i = i0 + wq * 16 + g + rr * 8;
            const float inv = rr ? inv1 : inv0;
            __half2 hv = __floats2half2_rn(o_acc[nb][rr*2] * inv, o_acc[nb][rr*2+1] * inv);
            const size_t o32 = ((size_t)(b * Sn + i) * NQ + h) * 64 + (d >> 1);
            ((uint32_t*)of)[o32] = *(uint32_t*)&hv;
        }
    }
}

// ---------------------------------------------------------------------------
extern "C" void kernel_launch(void* const* d_in, const int* in_sizes, int n_in,
                              void* d_out, int out_size)
{
    const float* x  = (const float*)d_in[0];
    const float* Wq = (const float*)d_in[1];
    const float* bq = (const float*)d_in[2];
    const float* Wk = (const float*)d_in[3];
    const float* bk = (const float*)d_in[4];
    const float* Wv = (const float*)d_in[5];
    const float* bv = (const float*)d_in[6];
    const float* Wo = (const float*)d_in[7];
    const float* bo = (const float*)d_in[8];
    float* out = (float*)d_out;

    float *qp, *kp, *vp;
    cudaGetSymbolAddress((void**)&qp, g_q);
    cudaGetSymbolAddress((void**)&kp, g_k);
    cudaGetSymbolAddress((void**)&vp, g_v);
    __half *xf, *of, *wq, *wk, *wv, *wo;
    cudaGetSymbolAddress((void**)&xf, g_xf); cudaGetSymbolAddress((void**)&of, g_of);
    cudaGetSymbolAddress((void**)&wq, g_wq); cudaGetSymbolAddress((void**)&wk, g_wk);
    cudaGetSymbolAddress((void**)&wv, g_wv); cudaGetSymbolAddress((void**)&wo, g_wo);
    __half *qh16, *ql16, *kf16, *vf16;
    cudaGetSymbolAddress((void**)&qh16, g_qh16); cudaGetSymbolAddress((void**)&ql16, g_ql16);
    cudaGetSymbolAddress((void**)&kf16, g_kf16); cudaGetSymbolAddress((void**)&vf16, g_vf16);

    cudaFuncSetAttribute(gemm_f16, cudaFuncAttributeMaxDynamicSharedMemorySize, GEMM_SMEM);
    cudaFuncSetAttribute(attn_mma, cudaFuncAttributeMaxDynamicSharedMemorySize, ATT_SMEM);

    // Converts
    const int n4x = Mrows * En / 4;
    cvt_f16<<<n4x / 1024, 1024>>>((const float4*)x, (uint2*)xf, n4x);
    dim3 tb(32, 8);
    cvt_f16_t<<<dim3(64, 64), tb>>>(Wq, wq, 2048, 2048);
    cvt_f16_t<<<dim3(16, 64), tb>>>(Wk, wk, 2048, 512);
    cvt_f16_t<<<dim3(16, 64), tb>>>(Wv, wv, 2048, 512);
    cvt_f16_t<<<dim3(64, 64), tb>>>(Wo, wo, 2048, 2048);

    // QKV projections (fp16 HMMA)
    gemm_f16<<<dim3(2048/128, Mrows/128), 256, GEMM_SMEM>>>(xf, wq, bq, qp, Mrows, 2048, En);
    gemm_f16<<<dim3(512/128,  Mrows/128), 256, GEMM_SMEM>>>(xf, wk, bk, kp, Mrows, 512, En);
    gemm_f16<<<dim3(512/128,  Mrows/128), 256, GEMM_SMEM>>>(xf, wv, bv, vp, Mrows, 512, En);

    // RoPE: q -> fp16 hi/lo (scaled), k -> fp16 single; v -> fp16 single
    {
        int totq = Mrows * NQ * 64;
        rope_split_q<<<(totq + 255) / 256, 256>>>(qp, qh16, ql16, NQ, totq, 0.08838834764831845f);
        int totk = Mrows * NKV * 64;
        rope_one<<<(totk + 255) / 256, 256>>>(kp, kf16, NKV, totk);
        int n4v = Mrows * NKV * HD / 4;
        cvt_f16<<<(n4v + 1023) / 1024, 1024>>>((const float4*)vp, (uint2*)vf16, n4v);
    }

    // Flash attention (fp16 2-term), fp16 output
    attn_mma<<<dim3(Sn/64, NQ, Bn), 128, ATT_SMEM>>>(qh16, ql16, kf16, vf16, of);

    // Output projection (fp16 HMMA)
    gemm_f16<<<dim3(2048/128, Mrows/128), 256, GEMM_SMEM>>>(of, wo, bo, out, Mrows, 2048, En);
}